// round 6
// baseline (speedup 1.0000x reference)
#include <cuda_runtime.h>
#include <cuda_bf16.h>
#include <math.h>
#include <stdint.h>

// Problem constants
#define BB 4
#define DD 768
#define GG 64
#define PP 256
#define HH 12
#define HD 64
#define GP (GG * PP)            // 16384
#define E3D (3 * DD)            // 2304
#define KK 768                  // K dim of both GEMMs
#define NT GP                   // N total of both GEMMs

// ---------------- scratch (allocation-free rule: __device__ globals) -------
__device__ __align__(256) float g_qkv[(size_t)BB * E3D * GP];          // [B, 3D, G*P]
__device__ __align__(256) __nv_bfloat16 g_xT_hi[(size_t)BB * GP * DD]; // x^T  [B, N, K]
__device__ __align__(256) __nv_bfloat16 g_xT_lo[(size_t)BB * GP * DD];
__device__ __align__(256) __nv_bfloat16 g_aT_hi[(size_t)BB * GP * DD]; // att^T [B, N, K]
__device__ __align__(256) __nv_bfloat16 g_aT_lo[(size_t)BB * GP * DD];
__device__ __align__(256) __nv_bfloat16 g_wq_hi[(size_t)E3D * DD];
__device__ __align__(256) __nv_bfloat16 g_wq_lo[(size_t)E3D * DD];
__device__ __align__(256) __nv_bfloat16 g_wp_hi[(size_t)DD * DD];
__device__ __align__(256) __nv_bfloat16 g_wp_lo[(size_t)DD * DD];
__device__ unsigned g_mask[(size_t)GG * PP * 8];   // packed keep-bits per (g,p)
__device__ int g_mask_dtype;                       // 0=u8,1=i32,2=f32,3=bf16

typedef unsigned long long ull;

// ---------------- small PTX helpers ----------------------------------------
__device__ __forceinline__ ull pack2(float x, float y) {
    ull r; asm("mov.b64 %0, {%1, %2};" : "=l"(r) : "f"(x), "f"(y)); return r;
}
__device__ __forceinline__ void unpack2(ull v, float& x, float& y) {
    asm("mov.b64 {%0, %1}, %2;" : "=f"(x), "=f"(y) : "l"(v));
}
__device__ __forceinline__ ull fma2(ull a, ull b, ull c) {
    ull d; asm("fma.rn.f32x2 %0, %1, %2, %3;" : "=l"(d) : "l"(a), "l"(b), "l"(c));
    return d;
}
__device__ __forceinline__ uint32_t smem_u32(const void* p) {
    uint32_t a;
    asm("{ .reg .u64 t; cvta.to.shared.u64 t, %1; cvt.u32.u64 %0, t; }"
        : "=r"(a) : "l"(p));
    return a;
}
__device__ __forceinline__ void ldsm4(uint32_t& r0, uint32_t& r1, uint32_t& r2,
                                      uint32_t& r3, uint32_t addr) {
    asm volatile("ldmatrix.sync.aligned.m8n8.x4.shared.b16 {%0,%1,%2,%3}, [%4];"
                 : "=r"(r0), "=r"(r1), "=r"(r2), "=r"(r3) : "r"(addr));
}
__device__ __forceinline__ void mma16816(float* c, const uint32_t* a, const uint32_t* b) {
    asm volatile(
        "mma.sync.aligned.m16n8k16.row.col.f32.bf16.bf16.f32 "
        "{%0,%1,%2,%3}, {%4,%5,%6,%7}, {%8,%9}, {%0,%1,%2,%3};"
        : "+f"(c[0]), "+f"(c[1]), "+f"(c[2]), "+f"(c[3])
        : "r"(a[0]), "r"(a[1]), "r"(a[2]), "r"(a[3]), "r"(b[0]), "r"(b[1]));
}
__device__ __forceinline__ void cpa16(uint32_t dst, const void* src) {
    asm volatile("cp.async.cg.shared.global [%0], [%1], 16;" :: "r"(dst), "l"(src));
}
#define CPA_COMMIT() asm volatile("cp.async.commit_group;" ::: "memory")
#define CPA_WAIT1()  asm volatile("cp.async.wait_group 1;" ::: "memory")
#define CPA_WAIT0()  asm volatile("cp.async.wait_group 0;" ::: "memory")

// Fast exp2 entirely on FMA/ALU pipes (magic-round, no conversion pipe).
// Valid for t <= ~30 (scores - max <= 0 here). Degree-6 poly on [-0.5, 0.5].
__device__ __forceinline__ float fexp2(float t) {
    t = fmaxf(t, -120.0f);
    float r = t + 12582912.0f;             // round-to-nearest-int in mantissa
    float f = t - (r - 12582912.0f);       // [-0.5, 0.5]
    int   sc = (__float_as_int(r) - 0x4B3FFF81) << 23;  // (n+127)<<23
    float p = 1.5403530e-4f;
    p = fmaf(p, f, 1.3333558e-3f);
    p = fmaf(p, f, 9.6181291e-3f);
    p = fmaf(p, f, 5.5504109e-2f);
    p = fmaf(p, f, 2.4022651e-1f);
    p = fmaf(p, f, 6.9314718e-1f);
    p = fmaf(p, f, 1.0f);
    return p * __int_as_float(sc);
}

// ---------------------------------------------------------------------------
// Mask dtype detection + packing
// ---------------------------------------------------------------------------
__global__ void detect_mask_dtype(const unsigned* __restrict__ m) {
    if (threadIdx.x != 0 || blockIdx.x != 0) return;
    int dt = 1;
    for (int i = 0; i < 1024; i++) {
        unsigned w = m[i];
        if (w == 0x3F800000u) { dt = 2; break; }
        if ((w & 0xFFFFu) == 0x3F80u || (w >> 16) == 0x3F80u) { dt = 3; break; }
        if (w > 1u) { dt = 0; break; }
    }
    g_mask_dtype = dt;
}

__global__ void pack_mask(const void* __restrict__ mraw) {
    int idx = blockIdx.x * blockDim.x + threadIdx.x;
    if (idx >= GG * PP * 8) return;
    int row = idx >> 3, w = idx & 7;
    int dt = g_mask_dtype;
    size_t base = (size_t)row * PP + w * 32;
    unsigned bits = 0;
    for (int t = 0; t < 32; t++) {
        bool keep;
        if (dt == 0)      keep = ((const unsigned char*)mraw)[base + t] != 0;
        else if (dt == 1) keep = ((const int*)mraw)[base + t] != 0;
        else if (dt == 2) keep = ((const float*)mraw)[base + t] != 0.0f;
        else              keep = ((const unsigned short*)mraw)[base + t] != 0;
        if (keep) bits |= 1u << t;
    }
    g_mask[idx] = bits;
}

// ---------------------------------------------------------------------------
// fp32 -> bf16 hi/lo split (weights, elementwise)
// ---------------------------------------------------------------------------
__global__ void conv_split(const float* __restrict__ in, __nv_bfloat16* __restrict__ hi,
                           __nv_bfloat16* __restrict__ lo, int n) {
    for (int i = blockIdx.x * blockDim.x + threadIdx.x; i < n; i += gridDim.x * blockDim.x) {
        float v = in[i];
        __nv_bfloat16 h = __float2bfloat16(v);
        hi[i] = h;
        lo[i] = __float2bfloat16(v - __bfloat162float(h));
    }
}

// x [B, K=768, N=16384] fp32 -> xT hi/lo [B, N, K] bf16 (transposed split)
__global__ void conv_xT(const float* __restrict__ x) {
    __shared__ float t[32][33];
    int bz = blockIdx.z;
    int n0 = blockIdx.x * 32, k0 = blockIdx.y * 32;
    int tx = threadIdx.x, ty = threadIdx.y;
    const float* xp = x + ((size_t)bz * DD + k0) * GP + n0;
    for (int i = ty; i < 32; i += 8) t[i][tx] = xp[(size_t)i * GP + tx];
    __syncthreads();
    for (int r = ty; r < 32; r += 8) {
        float v = t[tx][r];
        size_t o = ((size_t)bz * GP + n0 + r) * DD + k0 + tx;
        __nv_bfloat16 h = __float2bfloat16(v);
        g_xT_hi[o] = h;
        g_xT_lo[o] = __float2bfloat16(v - __bfloat162float(h));
    }
}

// ---------------------------------------------------------------------------
// Warp-MMA GEMM with cp.async 3-stage pipeline: C[bz] = A @ B[bz]^T (+ bias)
//   A  : [Mtot, K] bf16 hi/lo (K-major), shared over batch
//   B^T: [NT, K]  bf16 hi/lo (K-major), per batch
// CTA 128x128 (blockIdx.x = M-block for L2-friendly waves), 8 warps (2m x 4n),
// warp tile 64x32, K-chunk 32, 3 smem stages (40KB each, 80B padded rows).
// 3 split-products per step: Ah*Bh + Ah*Bl + Al*Bh (fp32 accumulate).
// ---------------------------------------------------------------------------
#define GOAH 0u
#define GOAL 10240u
#define GOBH 20480u
#define GOBL 30720u
#define GST  40960u

__global__ __launch_bounds__(256, 1) void gemm_mma(
    const __nv_bfloat16* __restrict__ Ah, const __nv_bfloat16* __restrict__ Al,
    const __nv_bfloat16* __restrict__ Bh_, const __nv_bfloat16* __restrict__ Bl_,
    float* __restrict__ C, const float* __restrict__ bias, int Mtot)
{
    extern __shared__ char smem[];
    const int tid = threadIdx.x;
    const int wid = tid >> 5, lane = tid & 31;
    const int bz = blockIdx.z;
    const int row0 = blockIdx.x * 128;   // M block (fastest -> wave shares B)
    const int col0 = blockIdx.y * 128;   // N block
    const __nv_bfloat16* Bh = Bh_ + (size_t)bz * NT * KK;
    const __nv_bfloat16* Bl = Bl_ + (size_t)bz * NT * KK;
    float* Cb = C + (size_t)bz * (size_t)Mtot * NT;

    const int warpM = (wid & 1) * 64;
    const int warpN = (wid >> 1) * 32;
    const uint32_t sb = smem_u32(smem);

    // per-thread load mapping: row = tid>>1, two 16B chunks at (tid&1)*32 bytes
    const int lr = tid >> 1;
    const int lc = (tid & 1) * 2;
    const __nv_bfloat16* pAh = Ah + (size_t)(row0 + lr) * KK + lc * 8;
    const __nv_bfloat16* pAl = Al + (size_t)(row0 + lr) * KK + lc * 8;
    const __nv_bfloat16* pBh = Bh + (size_t)(col0 + lr) * KK + lc * 8;
    const __nv_bfloat16* pBl = Bl + (size_t)(col0 + lr) * KK + lc * 8;
    const uint32_t ss = lr * 80 + lc * 16;

    // ldmatrix lane roles
    const int t0 = lane & 7, sel = lane >> 3;
    const uint32_t a_lrow = (warpM + t0 + ((sel & 1) << 3)) * 80 + ((sel >> 1) << 4);
    const uint32_t b_lrow = (warpN + t0 + ((sel >> 1) << 3)) * 80 + ((sel & 1) << 4);

    float acc[4][4][4];
#pragma unroll
    for (int i = 0; i < 4; i++)
#pragma unroll
        for (int j = 0; j < 4; j++)
#pragma unroll
            for (int r = 0; r < 4; r++) acc[i][j][r] = 0.0f;

    const int NCH = KK / 32;   // 24

    // issue stage for chunk c
    auto issue = [&](int c) {
        const uint32_t so = sb + (uint32_t)(c % 3) * GST + ss;
        const size_t ko = (size_t)c * 32;
        cpa16(so + GOAH,      pAh + ko);  cpa16(so + GOAH + 16, pAh + ko + 8);
        cpa16(so + GOAL,      pAl + ko);  cpa16(so + GOAL + 16, pAl + ko + 8);
        cpa16(so + GOBH,      pBh + ko);  cpa16(so + GOBH + 16, pBh + ko + 8);
        cpa16(so + GOBL,      pBl + ko);  cpa16(so + GOBL + 16, pBl + ko + 8);
    };

    issue(0); CPA_COMMIT();
    issue(1); CPA_COMMIT();

    for (int c = 0; c < NCH; c++) {
        if (c == NCH - 1) { CPA_WAIT0(); } else { CPA_WAIT1(); }
        __syncthreads();
        if (c + 2 < NCH) { issue(c + 2); CPA_COMMIT(); }

        const uint32_t so = sb + (uint32_t)(c % 3) * GST;
#pragma unroll
        for (int ks = 0; ks < 2; ks++) {
            uint32_t ah[4][4], al[4][4], bh[4][2], bl[4][2];
#pragma unroll
            for (int mt = 0; mt < 4; mt++) {
                const uint32_t ad = so + a_lrow + mt * 16 * 80 + ks * 32;
                ldsm4(ah[mt][0], ah[mt][1], ah[mt][2], ah[mt][3], ad + GOAH);
                ldsm4(al[mt][0], al[mt][1], al[mt][2], al[mt][3], ad + GOAL);
            }
#pragma unroll
            for (int ntp = 0; ntp < 2; ntp++) {
                const uint32_t bd = so + b_lrow + ntp * 16 * 80 + ks * 32;
                ldsm4(bh[2 * ntp][0], bh[2 * ntp][1], bh[2 * ntp + 1][0],
                      bh[2 * ntp + 1][1], bd + GOBH);
                ldsm4(bl[2 * ntp][0], bl[2 * ntp][1], bl[2 * ntp + 1][0],
                      bl[2 * ntp + 1][1], bd + GOBL);
            }
#pragma unroll
            for (int mt = 0; mt < 4; mt++)
#pragma unroll
                for (int nt = 0; nt < 4; nt++) {
                    mma16816(acc[mt][nt], ah[mt], bh[nt]);
                    mma16816(acc[mt][nt], ah[mt], bl[nt]);
                    mma16816(acc[mt][nt], al[mt], bh[nt]);
                }
        }
    }

    // epilogue: fragment -> gmem, bias by M-row
    const int gID = lane >> 2, tig = lane & 3;
#pragma unroll
    for (int mt = 0; mt < 4; mt++) {
#pragma unroll
        for (int half = 0; half < 2; half++) {
            const int row = row0 + warpM + mt * 16 + gID + half * 8;
            const float bv = bias ? __ldg(&bias[row]) : 0.0f;
            float* cp = Cb + (size_t)row * NT + col0 + warpN + tig * 2;
#pragma unroll
            for (int nt = 0; nt < 4; nt++) {
                float2 v = make_float2(acc[mt][nt][half * 2 + 0] + bv,
                                       acc[mt][nt][half * 2 + 1] + bv);
                *(float2*)(cp + nt * 8) = v;
            }
        }
    }
}

// ---------------------------------------------------------------------------
// Fused attention: one CTA per (b, h, g). 256 threads = 256 query rows.
// K in smem [hd][p] fp32; V in smem TRANSPOSED [key][hd] (68-float stride,
// 16B-aligned rows). 32-key blocks: QK^T and PV both as packed f32x2 with
// LDS.128 feeds. Online softmax in exp2 domain (FMA-pipe fexp2).
// Output written directly as transposed bf16 hi/lo split for GEMM2.
// ---------------------------------------------------------------------------
#define VS_STRIDE 68   // floats per V row (64 data + 4 pad): 272B, 16B-aligned

__global__ __launch_bounds__(256, 1) void attn_kernel(const float* __restrict__ qkv)
{
    const int g = blockIdx.x, h = blockIdx.y, b = blockIdx.z;
    const int p = threadIdx.x;

    extern __shared__ float sm[];
    float* Ks = sm;                     // [64][256]
    float* Vs = sm + 64 * 256;          // [256][VS_STRIDE]

    const size_t plane = (size_t)GP;
    const float* gq = qkv + ((size_t)b * E3D + h * HD) * plane + (size_t)g * PP;
    const float* gk = gq + (size_t)DD * plane;
    const float* gv = gq + (size_t)(2 * DD) * plane;

    // K: coalesced float4 over p, row-major smem
    // V: coalesced float4 over p, transposed scatter into Vs[key][hd]
    for (int idx = threadIdx.x; idx < 64 * 64; idx += 256) {
        int hd = idx >> 6;
        int p4 = (idx & 63) << 2;
        *(float4*)&Ks[hd * 256 + p4] = *(const float4*)&gk[(size_t)hd * plane + p4];
        float4 v = *(const float4*)&gv[(size_t)hd * plane + p4];
        Vs[(p4 + 0) * VS_STRIDE + hd] = v.x;
        Vs[(p4 + 1) * VS_STRIDE + hd] = v.y;
        Vs[(p4 + 2) * VS_STRIDE + hd] = v.z;
        Vs[(p4 + 3) * VS_STRIDE + hd] = v.w;
    }

    const float CC = 0.18033688011112042f;  // (1/8) * log2(e)
    float q[HD];
#pragma unroll
    for (int d = 0; d < HD; d++) q[d] = gq[(size_t)d * plane + p] * CC;

    unsigned mbits[8];
    {
        const unsigned* mrow = g_mask + ((size_t)g * PP + p) * 8;
#pragma unroll
        for (int i = 0; i < 8; i++) mbits[i] = mrow[i];
    }

    __syncthreads();

    float m = -INFINITY, l = 0.0f;
    ull o2[32];
#pragma unroll
    for (int i = 0; i < 32; i++) o2[i] = 0ull;

    for (int kb = 0; kb < 8; kb++) {        // 8 blocks of 32 keys
        // ---- QK^T for 32 keys: s2[e] = scores for key pair (2e, 2e+1)
        ull s2[16];
#pragma unroll
        for (int e = 0; e < 16; e++) s2[e] = 0ull;
#pragma unroll 8
        for (int d = 0; d < HD; d++) {
            const ull qq = pack2(q[d], q[d]);
            const ulonglong2* kp = (const ulonglong2*)(Ks + d * 256 + kb * 32);
#pragma unroll
            for (int e2 = 0; e2 < 8; e2++) {
                ulonglong2 kk = kp[e2];
                s2[2 * e2 + 0] = fma2(qq, kk.x, s2[2 * e2 + 0]);
                s2[2 * e2 + 1] = fma2(qq, kk.y, s2[2 * e2 + 1]);
            }
        }
        float s[32];
#pragma unroll
        for (int e = 0; e < 16; e++) unpack2(s2[e], s[2 * e], s[2 * e + 1]);

        const unsigned mw = mbits[kb];
#pragma unroll
        for (int t = 0; t < 32; t++)
            if (!((mw >> t) & 1u)) s[t] = -1e30f;

        // block max (tree)
        float mx = s[0];
#pragma unroll
        for (int t = 1; t < 32; t++) mx = fmaxf(mx, s[t]);

        if (mx > m) {
            const float al = fexp2(m - mx);
            l *= al;
            const ull ap = pack2(al, al);
#pragma unroll
            for (int i = 0; i < 32; i++) o2[i] = fma2(ap, o2[i], 0ull);
            m = mx;
        }

        float ws = 0.0f;
#pragma unroll
        for (int t = 0; t < 32; t++) {
            s[t] = fexp2(s[t] - m);
            ws += s[t];
        }
        l += ws;

        // ---- PV: 32 keys, V rows contiguous over hd
#pragma unroll 4
        for (int t = 0; t < 32; t++) {
            const ull wp = pack2(s[t], s[t]);
            const ulonglong2* vr = (const ulonglong2*)(Vs + (kb * 32 + t) * VS_STRIDE);
#pragma unroll
            for (int e2 = 0; e2 < 16; e2++) {
                ulonglong2 vv = vr[e2];
                o2[2 * e2 + 0] = fma2(wp, vv.x, o2[2 * e2 + 0]);
                o2[2 * e2 + 1] = fma2(wp, vv.y, o2[2 * e2 + 1]);
            }
        }
    }

    // epilogue: normalize, bf16 hi/lo split, transposed write
    const float inv = 1.0f / l;
    const size_t orow = ((size_t)b * GP + (size_t)g * PP + p) * DD + h * HD;
#pragma unroll
    for (int e = 0; e < 32; e++) {
        float v0, v1;
        unpack2(o2[e], v0, v1);
        v0 *= inv; v1 *= inv;
        __nv_bfloat16 h0 = __float2bfloat16(v0), h1 = __float2bfloat16(v1);
        __nv_bfloat162 hh; hh.x = h0; hh.y = h1;
        __nv_bfloat162 ll2;
        ll2.x = __float2bfloat16(v0 - __bfloat162float(h0));
        ll2.y = __float2bfloat16(v1 - __bfloat162float(h1));
        *(__nv_bfloat162*)(&g_aT_hi[orow + 2 * e]) = hh;
        *(__nv_bfloat162*)(&g_aT_lo[orow + 2 * e]) = ll2;
    }
}

// ---------------------------------------------------------------------------
extern "C" void kernel_launch(void* const* d_in, const int* in_sizes, int n_in,
                              void* d_out, int out_size)
{
    const float* x      = (const float*)d_in[0];
    const void*  mask   = d_in[1];
    const float* w_qkv  = (const float*)d_in[2];
    const float* w_proj = (const float*)d_in[3];
    const float* b_proj = (const float*)d_in[4];
    float*       out    = (float*)d_out;

    float *qkvbuf = nullptr;
    __nv_bfloat16 *xth, *xtl, *ath, *atl, *wqh, *wql, *wph, *wpl;
    cudaGetSymbolAddress((void**)&qkvbuf, g_qkv);
    cudaGetSymbolAddress((void**)&xth, g_xT_hi);
    cudaGetSymbolAddress((void**)&xtl, g_xT_lo);
    cudaGetSymbolAddress((void**)&ath, g_aT_hi);
    cudaGetSymbolAddress((void**)&atl, g_aT_lo);
    cudaGetSymbolAddress((void**)&wqh, g_wq_hi);
    cudaGetSymbolAddress((void**)&wql, g_wq_lo);
    cudaGetSymbolAddress((void**)&wph, g_wp_hi);
    cudaGetSymbolAddress((void**)&wpl, g_wp_lo);

    // 0) mask dtype detection + bit packing
    detect_mask_dtype<<<1, 32>>>((const unsigned*)mask);
    pack_mask<<<(GG * PP * 8 + 255) / 256, 256>>>(mask);

    // 1) bf16 hi/lo conversions: weights + transposed x
    conv_split<<<1024, 256>>>(w_qkv, wqh, wql, E3D * DD);
    conv_split<<<1024, 256>>>(w_proj, wph, wpl, DD * DD);
    conv_xT<<<dim3(GP / 32, DD / 32, BB), dim3(32, 8)>>>(x);

    const int GEMM_SMEM = 3 * 40960;                       // 120KB, 3 stages
    const int ATTN_SMEM = (64 * 256 + 256 * VS_STRIDE) * 4; // 135168B
    cudaFuncSetAttribute(gemm_mma, cudaFuncAttributeMaxDynamicSharedMemorySize, GEMM_SMEM);
    cudaFuncSetAttribute(attn_kernel, cudaFuncAttributeMaxDynamicSharedMemorySize, ATTN_SMEM);

    // 2) QKV projection: [2304 x 768] @ [768 x 16384] per batch (M-block fastest)
    gemm_mma<<<dim3(E3D / 128, NT / 128, BB), 256, GEMM_SMEM>>>(
        wqh, wql, xth, xtl, qkvbuf, nullptr, E3D);

    // 3) fused masked attention per (b, h, g) -> transposed bf16 split output
    attn_kernel<<<dim3(GG, HH, BB), 256, ATTN_SMEM>>>(qkvbuf);

    // 4) output projection + bias
    gemm_mma<<<dim3(DD / 128, NT / 128, BB), 256, GEMM_SMEM>>>(
        wph, wpl, ath, atl, out, b_proj, DD);
}

// round 7
// speedup vs baseline: 1.0000x; 1.0000x over previous
#include <cuda_runtime.h>
#include <cuda_bf16.h>
#include <math.h>
#include <stdint.h>

// Problem constants
#define BB 4
#define DD 768
#define GG 64
#define PP 256
#define HH 12
#define HD 64
#define GP (GG * PP)            // 16384
#define E3D (3 * DD)            // 2304
#define KK 768                  // K dim of both GEMMs
#define NT GP                   // N total of both GEMMs

// ---------------- scratch (allocation-free rule: __device__ globals) -------
__device__ __align__(256) float g_qkv[(size_t)BB * E3D * GP];          // [B, 3D, G*P]
__device__ __align__(256) __nv_bfloat16 g_xT_hi[(size_t)BB * GP * DD]; // x^T  [B, N, K]
__device__ __align__(256) __nv_bfloat16 g_xT_lo[(size_t)BB * GP * DD];
__device__ __align__(256) __nv_bfloat16 g_aT_hi[(size_t)BB * GP * DD]; // att^T [B, N, K]
__device__ __align__(256) __nv_bfloat16 g_aT_lo[(size_t)BB * GP * DD];
__device__ __align__(256) __nv_bfloat16 g_wq_hi[(size_t)E3D * DD];
__device__ __align__(256) __nv_bfloat16 g_wq_lo[(size_t)E3D * DD];
__device__ __align__(256) __nv_bfloat16 g_wp_hi[(size_t)DD * DD];
__device__ __align__(256) __nv_bfloat16 g_wp_lo[(size_t)DD * DD];
__device__ unsigned g_mask[(size_t)GG * PP * 8];   // packed keep-bits per (g,p)
__device__ int g_mask_dtype;                       // 0=u8,1=i32,2=f32,3=bf16

typedef unsigned long long ull;

// ---------------- small PTX helpers ----------------------------------------
__device__ __forceinline__ ull pack2(float x, float y) {
    ull r; asm("mov.b64 %0, {%1, %2};" : "=l"(r) : "f"(x), "f"(y)); return r;
}
__device__ __forceinline__ void unpack2(ull v, float& x, float& y) {
    asm("mov.b64 {%0, %1}, %2;" : "=f"(x), "=f"(y) : "l"(v));
}
__device__ __forceinline__ ull fma2(ull a, ull b, ull c) {
    ull d; asm("fma.rn.f32x2 %0, %1, %2, %3;" : "=l"(d) : "l"(a), "l"(b), "l"(c));
    return d;
}
__device__ __forceinline__ uint32_t smem_u32(const void* p) {
    uint32_t a;
    asm("{ .reg .u64 t; cvta.to.shared.u64 t, %1; cvt.u32.u64 %0, t; }"
        : "=r"(a) : "l"(p));
    return a;
}
__device__ __forceinline__ void ldsm4(uint32_t& r0, uint32_t& r1, uint32_t& r2,
                                      uint32_t& r3, uint32_t addr) {
    asm volatile("ldmatrix.sync.aligned.m8n8.x4.shared.b16 {%0,%1,%2,%3}, [%4];"
                 : "=r"(r0), "=r"(r1), "=r"(r2), "=r"(r3) : "r"(addr));
}
__device__ __forceinline__ void mma16816(float* c, const uint32_t* a, const uint32_t* b) {
    asm volatile(
        "mma.sync.aligned.m16n8k16.row.col.f32.bf16.bf16.f32 "
        "{%0,%1,%2,%3}, {%4,%5,%6,%7}, {%8,%9}, {%0,%1,%2,%3};"
        : "+f"(c[0]), "+f"(c[1]), "+f"(c[2]), "+f"(c[3])
        : "r"(a[0]), "r"(a[1]), "r"(a[2]), "r"(a[3]), "r"(b[0]), "r"(b[1]));
}
__device__ __forceinline__ void cpa16(uint32_t dst, const void* src) {
    asm volatile("cp.async.cg.shared.global [%0], [%1], 16;" :: "r"(dst), "l"(src));
}
#define CPA_COMMIT() asm volatile("cp.async.commit_group;" ::: "memory")
#define CPA_WAIT1()  asm volatile("cp.async.wait_group 1;" ::: "memory")
#define CPA_WAIT0()  asm volatile("cp.async.wait_group 0;" ::: "memory")

// Fast exp2 entirely on FMA/ALU pipes (magic-constant round, no cvt pipe).
// Valid for t in [-126, ~30]; here t <= 0, clamped at -120.
__device__ __forceinline__ float fexp2(float t) {
    t = fmaxf(t, -120.0f);
    float r = t + 12582912.0f;             // round-to-nearest-int in mantissa
    float f = t - (r - 12582912.0f);       // [-0.5, 0.5]
    int   sc = (__float_as_int(r) - 0x4B3FFF81) << 23;  // (n+127)<<23
    float p = 1.5403530e-4f;
    p = fmaf(p, f, 1.3333558e-3f);
    p = fmaf(p, f, 9.6181291e-3f);
    p = fmaf(p, f, 5.5504109e-2f);
    p = fmaf(p, f, 2.4022651e-1f);
    p = fmaf(p, f, 6.9314718e-1f);
    p = fmaf(p, f, 1.0f);
    return p * __int_as_float(sc);
}

// ---------------------------------------------------------------------------
// Mask dtype detection + packing
// ---------------------------------------------------------------------------
__global__ void detect_mask_dtype(const unsigned* __restrict__ m) {
    if (threadIdx.x != 0 || blockIdx.x != 0) return;
    int dt = 1;
    for (int i = 0; i < 1024; i++) {
        unsigned w = m[i];
        if (w == 0x3F800000u) { dt = 2; break; }
        if ((w & 0xFFFFu) == 0x3F80u || (w >> 16) == 0x3F80u) { dt = 3; break; }
        if (w > 1u) { dt = 0; break; }
    }
    g_mask_dtype = dt;
}

__global__ void pack_mask(const void* __restrict__ mraw) {
    int idx = blockIdx.x * blockDim.x + threadIdx.x;
    if (idx >= GG * PP * 8) return;
    int row = idx >> 3, w = idx & 7;
    int dt = g_mask_dtype;
    size_t base = (size_t)row * PP + w * 32;
    unsigned bits = 0;
    for (int t = 0; t < 32; t++) {
        bool keep;
        if (dt == 0)      keep = ((const unsigned char*)mraw)[base + t] != 0;
        else if (dt == 1) keep = ((const int*)mraw)[base + t] != 0;
        else if (dt == 2) keep = ((const float*)mraw)[base + t] != 0.0f;
        else              keep = ((const unsigned short*)mraw)[base + t] != 0;
        if (keep) bits |= 1u << t;
    }
    g_mask[idx] = bits;
}

// ---------------------------------------------------------------------------
// fp32 -> bf16 hi/lo split (weights, elementwise)
// ---------------------------------------------------------------------------
__global__ void conv_split(const float* __restrict__ in, __nv_bfloat16* __restrict__ hi,
                           __nv_bfloat16* __restrict__ lo, int n) {
    for (int i = blockIdx.x * blockDim.x + threadIdx.x; i < n; i += gridDim.x * blockDim.x) {
        float v = in[i];
        __nv_bfloat16 h = __float2bfloat16(v);
        hi[i] = h;
        lo[i] = __float2bfloat16(v - __bfloat162float(h));
    }
}

// x [B, K=768, N=16384] fp32 -> xT hi/lo [B, N, K] bf16 (transposed split)
__global__ void conv_xT(const float* __restrict__ x) {
    __shared__ float t[32][33];
    int bz = blockIdx.z;
    int n0 = blockIdx.x * 32, k0 = blockIdx.y * 32;
    int tx = threadIdx.x, ty = threadIdx.y;
    const float* xp = x + ((size_t)bz * DD + k0) * GP + n0;
    for (int i = ty; i < 32; i += 8) t[i][tx] = xp[(size_t)i * GP + tx];
    __syncthreads();
    for (int r = ty; r < 32; r += 8) {
        float v = t[tx][r];
        size_t o = ((size_t)bz * GP + n0 + r) * DD + k0 + tx;
        __nv_bfloat16 h = __float2bfloat16(v);
        g_xT_hi[o] = h;
        g_xT_lo[o] = __float2bfloat16(v - __bfloat162float(h));
    }
}

// ---------------------------------------------------------------------------
// Warp-MMA GEMM with cp.async 3-stage pipeline: C[bz] = A @ B[bz]^T (+ bias)
// CTA 128x128 (blockIdx.x = M-block -> wave shares B tiles in L2), 8 warps
// (2m x 4n), warp tile 64x32, K-chunk 32, 3 smem stages (40KB, 80B rows).
// 3 split-products per step: Ah*Bh + Ah*Bl + Al*Bh (fp32 accumulate).
// ---------------------------------------------------------------------------
#define GOAH 0u
#define GOAL 10240u
#define GOBH 20480u
#define GOBL 30720u
#define GST  40960u

__global__ __launch_bounds__(256, 1) void gemm_mma(
    const __nv_bfloat16* __restrict__ Ah, const __nv_bfloat16* __restrict__ Al,
    const __nv_bfloat16* __restrict__ Bh_, const __nv_bfloat16* __restrict__ Bl_,
    float* __restrict__ C, const float* __restrict__ bias, int Mtot)
{
    extern __shared__ char smem[];
    const int tid = threadIdx.x;
    const int wid = tid >> 5, lane = tid & 31;
    const int bz = blockIdx.z;
    const int row0 = blockIdx.x * 128;   // M block (fastest)
    const int col0 = blockIdx.y * 128;   // N block
    const __nv_bfloat16* Bh = Bh_ + (size_t)bz * NT * KK;
    const __nv_bfloat16* Bl = Bl_ + (size_t)bz * NT * KK;
    float* Cb = C + (size_t)bz * (size_t)Mtot * NT;

    const int warpM = (wid & 1) * 64;
    const int warpN = (wid >> 1) * 32;
    const uint32_t sb = smem_u32(smem);

    const int lr = tid >> 1;
    const int lc = (tid & 1) * 2;
    const __nv_bfloat16* pAh = Ah + (size_t)(row0 + lr) * KK + lc * 8;
    const __nv_bfloat16* pAl = Al + (size_t)(row0 + lr) * KK + lc * 8;
    const __nv_bfloat16* pBh = Bh + (size_t)(col0 + lr) * KK + lc * 8;
    const __nv_bfloat16* pBl = Bl + (size_t)(col0 + lr) * KK + lc * 8;
    const uint32_t ss = lr * 80 + lc * 16;

    const int t0 = lane & 7, sel = lane >> 3;
    const uint32_t a_lrow = (warpM + t0 + ((sel & 1) << 3)) * 80 + ((sel >> 1) << 4);
    const uint32_t b_lrow = (warpN + t0 + ((sel >> 1) << 3)) * 80 + ((sel & 1) << 4);

    float acc[4][4][4];
#pragma unroll
    for (int i = 0; i < 4; i++)
#pragma unroll
        for (int j = 0; j < 4; j++)
#pragma unroll
            for (int r = 0; r < 4; r++) acc[i][j][r] = 0.0f;

    const int NCH = KK / 32;   // 24

    auto issue = [&](int c) {
        const uint32_t so = sb + (uint32_t)(c % 3) * GST + ss;
        const size_t ko = (size_t)c * 32;
        cpa16(so + GOAH,      pAh + ko);  cpa16(so + GOAH + 16, pAh + ko + 8);
        cpa16(so + GOAL,      pAl + ko);  cpa16(so + GOAL + 16, pAl + ko + 8);
        cpa16(so + GOBH,      pBh + ko);  cpa16(so + GOBH + 16, pBh + ko + 8);
        cpa16(so + GOBL,      pBl + ko);  cpa16(so + GOBL + 16, pBl + ko + 8);
    };

    issue(0); CPA_COMMIT();
    issue(1); CPA_COMMIT();

    for (int c = 0; c < NCH; c++) {
        if (c == NCH - 1) { CPA_WAIT0(); } else { CPA_WAIT1(); }
        __syncthreads();
        if (c + 2 < NCH) { issue(c + 2); CPA_COMMIT(); }

        const uint32_t so = sb + (uint32_t)(c % 3) * GST;
#pragma unroll
        for (int ks = 0; ks < 2; ks++) {
            uint32_t ah[4][4], al[4][4], bh[4][2], bl[4][2];
#pragma unroll
            for (int mt = 0; mt < 4; mt++) {
                const uint32_t ad = so + a_lrow + mt * 16 * 80 + ks * 32;
                ldsm4(ah[mt][0], ah[mt][1], ah[mt][2], ah[mt][3], ad + GOAH);
                ldsm4(al[mt][0], al[mt][1], al[mt][2], al[mt][3], ad + GOAL);
            }
#pragma unroll
            for (int ntp = 0; ntp < 2; ntp++) {
                const uint32_t bd = so + b_lrow + ntp * 16 * 80 + ks * 32;
                ldsm4(bh[2 * ntp][0], bh[2 * ntp][1], bh[2 * ntp + 1][0],
                      bh[2 * ntp + 1][1], bd + GOBH);
                ldsm4(bl[2 * ntp][0], bl[2 * ntp][1], bl[2 * ntp + 1][0],
                      bl[2 * ntp + 1][1], bd + GOBL);
            }
#pragma unroll
            for (int mt = 0; mt < 4; mt++)
#pragma unroll
                for (int nt = 0; nt < 4; nt++) {
                    mma16816(acc[mt][nt], ah[mt], bh[nt]);
                    mma16816(acc[mt][nt], ah[mt], bl[nt]);
                    mma16816(acc[mt][nt], al[mt], bh[nt]);
                }
        }
    }

    const int gID = lane >> 2, tig = lane & 3;
#pragma unroll
    for (int mt = 0; mt < 4; mt++) {
#pragma unroll
        for (int half = 0; half < 2; half++) {
            const int row = row0 + warpM + mt * 16 + gID + half * 8;
            const float bv = bias ? __ldg(&bias[row]) : 0.0f;
            float* cp = Cb + (size_t)row * NT + col0 + warpN + tig * 2;
#pragma unroll
            for (int nt = 0; nt < 4; nt++) {
                float2 v = make_float2(acc[mt][nt][half * 2 + 0] + bv,
                                       acc[mt][nt][half * 2 + 1] + bv);
                *(float2*)(cp + nt * 8) = v;
            }
        }
    }
}

// ---------------------------------------------------------------------------
// Fused attention (R4 formulation — no spills): one CTA per (b, h, g).
// 256 threads = 256 query rows. K/V in 128KB smem ([hd][p] fp32).
// QK^T via packed f32x2 on smem pairs; online softmax in exp2 domain.
// Output written directly as transposed bf16 hi/lo split for GEMM2.
// ---------------------------------------------------------------------------
__global__ __launch_bounds__(256, 1) void attn_kernel(const float* __restrict__ qkv)
{
    const int g = blockIdx.x, h = blockIdx.y, b = blockIdx.z;
    const int p = threadIdx.x;

    extern __shared__ float sm[];
    float* Ks = sm;              // [64][256]
    float* Vs = sm + 64 * 256;   // [64][256]

    const size_t plane = (size_t)GP;
    const float* gq = qkv + ((size_t)b * E3D + h * HD) * plane + (size_t)g * PP;
    const float* gk = gq + (size_t)DD * plane;
    const float* gv = gq + (size_t)(2 * DD) * plane;

    for (int idx = threadIdx.x; idx < 64 * 64; idx += 256) {
        int hd = idx >> 6;
        int p4 = (idx & 63) << 2;
        *(float4*)&Ks[hd * 256 + p4] = *(const float4*)&gk[(size_t)hd * plane + p4];
        *(float4*)&Vs[hd * 256 + p4] = *(const float4*)&gv[(size_t)hd * plane + p4];
    }

    const float CC = 0.18033688011112042f;  // (1/8) * log2(e)
    float q[HD];
#pragma unroll
    for (int d = 0; d < HD; d++) q[d] = gq[(size_t)d * plane + p] * CC;

    unsigned mbits[8];
    {
        const unsigned* mrow = g_mask + ((size_t)g * PP + p) * 8;
#pragma unroll
        for (int i = 0; i < 8; i++) mbits[i] = mrow[i];
    }

    __syncthreads();

    float m = -INFINITY, l = 0.0f;
    float o[HD];
#pragma unroll
    for (int d = 0; d < HD; d++) o[d] = 0.0f;

    const ull* K2 = (const ull*)Ks;
    const float4* V4 = (const float4*)Vs;

    for (int j4 = 0; j4 < 64; j4++) {
        ull s01 = 0ull, s23 = 0ull;
#pragma unroll
        for (int d = 0; d < HD; d++) {
            ull qq = pack2(q[d], q[d]);
            s01 = fma2(qq, K2[d * 128 + j4 * 2 + 0], s01);
            s23 = fma2(qq, K2[d * 128 + j4 * 2 + 1], s23);
        }
        float s0, s1, s2, s3;
        unpack2(s01, s0, s1);
        unpack2(s23, s2, s3);

        unsigned kp = (mbits[j4 >> 3] >> ((j4 & 7) << 2)) & 0xFu;
        if (!(kp & 1u)) s0 = -1e30f;
        if (!(kp & 2u)) s1 = -1e30f;
        if (!(kp & 4u)) s2 = -1e30f;
        if (!(kp & 8u)) s3 = -1e30f;

        float mx = fmaxf(fmaxf(s0, s1), fmaxf(s2, s3));
        if (mx > m) {
            float al = fexp2(m - mx);
            l *= al;
#pragma unroll
            for (int d = 0; d < HD; d++) o[d] *= al;
            m = mx;
        }
        float w0 = fexp2(s0 - m);
        float w1 = fexp2(s1 - m);
        float w2 = fexp2(s2 - m);
        float w3 = fexp2(s3 - m);
        l += (w0 + w1) + (w2 + w3);
#pragma unroll
        for (int d = 0; d < HD; d++) {
            float4 vv = V4[d * 64 + j4];
            o[d] += (w0 * vv.x + w1 * vv.y) + (w2 * vv.z + w3 * vv.w);
        }
    }

    // epilogue: normalize, bf16 hi/lo split, transposed write
    const float inv = 1.0f / l;
    const size_t orow = ((size_t)b * GP + (size_t)g * PP + p) * DD + h * HD;
#pragma unroll
    for (int d = 0; d < HD; d += 2) {
        float v0 = o[d] * inv, v1 = o[d + 1] * inv;
        __nv_bfloat16 h0 = __float2bfloat16(v0), h1 = __float2bfloat16(v1);
        __nv_bfloat162 hh; hh.x = h0; hh.y = h1;
        __nv_bfloat162 ll2;
        ll2.x = __float2bfloat16(v0 - __bfloat162float(h0));
        ll2.y = __float2bfloat16(v1 - __bfloat162float(h1));
        *(__nv_bfloat162*)(&g_aT_hi[orow + d]) = hh;
        *(__nv_bfloat162*)(&g_aT_lo[orow + d]) = ll2;
    }
}

// ---------------------------------------------------------------------------
extern "C" void kernel_launch(void* const* d_in, const int* in_sizes, int n_in,
                              void* d_out, int out_size)
{
    const float* x      = (const float*)d_in[0];
    const void*  mask   = d_in[1];
    const float* w_qkv  = (const float*)d_in[2];
    const float* w_proj = (const float*)d_in[3];
    const float* b_proj = (const float*)d_in[4];
    float*       out    = (float*)d_out;

    float *qkvbuf = nullptr;
    __nv_bfloat16 *xth, *xtl, *ath, *atl, *wqh, *wql, *wph, *wpl;
    cudaGetSymbolAddress((void**)&qkvbuf, g_qkv);
    cudaGetSymbolAddress((void**)&xth, g_xT_hi);
    cudaGetSymbolAddress((void**)&xtl, g_xT_lo);
    cudaGetSymbolAddress((void**)&ath, g_aT_hi);
    cudaGetSymbolAddress((void**)&atl, g_aT_lo);
    cudaGetSymbolAddress((void**)&wqh, g_wq_hi);
    cudaGetSymbolAddress((void**)&wql, g_wq_lo);
    cudaGetSymbolAddress((void**)&wph, g_wp_hi);
    cudaGetSymbolAddress((void**)&wpl, g_wp_lo);

    // 0) mask dtype detection + bit packing
    detect_mask_dtype<<<1, 32>>>((const unsigned*)mask);
    pack_mask<<<(GG * PP * 8 + 255) / 256, 256>>>(mask);

    // 1) bf16 hi/lo conversions: weights + transposed x
    conv_split<<<1024, 256>>>(w_qkv, wqh, wql, E3D * DD);
    conv_split<<<1024, 256>>>(w_proj, wph, wpl, DD * DD);
    conv_xT<<<dim3(GP / 32, DD / 32, BB), dim3(32, 8)>>>(x);

    const int GEMM_SMEM = 3 * 40960;         // 120KB, 3 stages
    const int ATTN_SMEM = 131072;            // 128KB K+V
    cudaFuncSetAttribute(gemm_mma, cudaFuncAttributeMaxDynamicSharedMemorySize, GEMM_SMEM);
    cudaFuncSetAttribute(attn_kernel, cudaFuncAttributeMaxDynamicSharedMemorySize, ATTN_SMEM);

    // 2) QKV projection: [2304 x 768] @ [768 x 16384] per batch (M-block fastest)
    gemm_mma<<<dim3(E3D / 128, NT / 128, BB), 256, GEMM_SMEM>>>(
        wqh, wql, xth, xtl, qkvbuf, nullptr, E3D);

    // 3) fused masked attention per (b, h, g) -> transposed bf16 split output
    attn_kernel<<<dim3(GG, HH, BB), 256, ATTN_SMEM>>>(qkvbuf);

    // 4) output projection + bias
    gemm_mma<<<dim3(DD / 128, NT / 128, BB), 256, GEMM_SMEM>>>(
        wph, wpl, ath, atl, out, b_proj, DD);
}

// round 8
// speedup vs baseline: 1.1996x; 1.1995x over previous
#include <cuda_runtime.h>
#include <cuda_fp16.h>
#include <math.h>
#include <stdint.h>

// Problem constants
#define BB 4
#define DD 768
#define GG 64
#define PP 256
#define HH 12
#define HD 64
#define GP (GG * PP)            // 16384
#define E3D (3 * DD)            // 2304
#define KK 768                  // K dim of both GEMMs
#define NT GP                   // N total of both GEMMs

// ---------------- scratch (allocation-free rule: __device__ globals) -------
__device__ __align__(256) float g_qkv[(size_t)BB * E3D * GP];   // [B, 3D, G*P]
__device__ __align__(256) __half g_xT[(size_t)BB * GP * DD];    // x^T [B,N,K] fp16
__device__ __align__(256) __half g_aT[(size_t)BB * GP * DD];    // att^T fp16
__device__ __align__(256) __half g_wq_hi[(size_t)E3D * DD];
__device__ __align__(256) __half g_wq_lo[(size_t)E3D * DD];
__device__ __align__(256) __half g_wp_hi[(size_t)DD * DD];
__device__ __align__(256) __half g_wp_lo[(size_t)DD * DD];
__device__ unsigned g_mask[(size_t)GG * PP * 8];   // packed keep-bits per (g,p)
__device__ int g_mask_dtype;                       // 0=u8,1=i32,2=f32,3=bf16

typedef unsigned long long ull;

// ---------------- small PTX helpers ----------------------------------------
__device__ __forceinline__ ull pack2(float x, float y) {
    ull r; asm("mov.b64 %0, {%1, %2};" : "=l"(r) : "f"(x), "f"(y)); return r;
}
__device__ __forceinline__ void unpack2(ull v, float& x, float& y) {
    asm("mov.b64 {%0, %1}, %2;" : "=f"(x), "=f"(y) : "l"(v));
}
__device__ __forceinline__ ull fma2(ull a, ull b, ull c) {
    ull d; asm("fma.rn.f32x2 %0, %1, %2, %3;" : "=l"(d) : "l"(a), "l"(b), "l"(c));
    return d;
}
__device__ __forceinline__ uint32_t smem_u32(const void* p) {
    uint32_t a;
    asm("{ .reg .u64 t; cvta.to.shared.u64 t, %1; cvt.u32.u64 %0, t; }"
        : "=r"(a) : "l"(p));
    return a;
}
__device__ __forceinline__ void ldsm4(uint32_t& r0, uint32_t& r1, uint32_t& r2,
                                      uint32_t& r3, uint32_t addr) {
    asm volatile("ldmatrix.sync.aligned.m8n8.x4.shared.b16 {%0,%1,%2,%3}, [%4];"
                 : "=r"(r0), "=r"(r1), "=r"(r2), "=r"(r3) : "r"(addr));
}
__device__ __forceinline__ void mma16816(float* c, const uint32_t* a, const uint32_t* b) {
    asm volatile(
        "mma.sync.aligned.m16n8k16.row.col.f32.f16.f16.f32 "
        "{%0,%1,%2,%3}, {%4,%5,%6,%7}, {%8,%9}, {%0,%1,%2,%3};"
        : "+f"(c[0]), "+f"(c[1]), "+f"(c[2]), "+f"(c[3])
        : "r"(a[0]), "r"(a[1]), "r"(a[2]), "r"(a[3]), "r"(b[0]), "r"(b[1]));
}

// Fast exp2 entirely on FMA/ALU pipes (magic-constant round, no cvt pipe).
__device__ __forceinline__ float fexp2(float t) {
    t = fmaxf(t, -120.0f);
    float r = t + 12582912.0f;             // round-to-nearest-int in mantissa
    float f = t - (r - 12582912.0f);       // [-0.5, 0.5]
    int   sc = (__float_as_int(r) - 0x4B3FFF81) << 23;  // (n+127)<<23
    float p = 1.5403530e-4f;
    p = fmaf(p, f, 1.3333558e-3f);
    p = fmaf(p, f, 9.6181291e-3f);
    p = fmaf(p, f, 5.5504109e-2f);
    p = fmaf(p, f, 2.4022651e-1f);
    p = fmaf(p, f, 6.9314718e-1f);
    p = fmaf(p, f, 1.0f);
    return p * __int_as_float(sc);
}

// ---------------------------------------------------------------------------
// Mask dtype detection + packing
// ---------------------------------------------------------------------------
__global__ void detect_mask_dtype(const unsigned* __restrict__ m) {
    if (threadIdx.x != 0 || blockIdx.x != 0) return;
    int dt = 1;
    for (int i = 0; i < 1024; i++) {
        unsigned w = m[i];
        if (w == 0x3F800000u) { dt = 2; break; }
        if ((w & 0xFFFFu) == 0x3F80u || (w >> 16) == 0x3F80u) { dt = 3; break; }
        if (w > 1u) { dt = 0; break; }
    }
    g_mask_dtype = dt;
}

__global__ void pack_mask(const void* __restrict__ mraw) {
    int idx = blockIdx.x * blockDim.x + threadIdx.x;
    if (idx >= GG * PP * 8) return;
    int row = idx >> 3, w = idx & 7;
    int dt = g_mask_dtype;
    size_t base = (size_t)row * PP + w * 32;
    unsigned bits = 0;
    for (int t = 0; t < 32; t++) {
        bool keep;
        if (dt == 0)      keep = ((const unsigned char*)mraw)[base + t] != 0;
        else if (dt == 1) keep = ((const int*)mraw)[base + t] != 0;
        else if (dt == 2) keep = ((const float*)mraw)[base + t] != 0.0f;
        else              keep = ((const unsigned short*)mraw)[base + t] != 0;
        if (keep) bits |= 1u << t;
    }
    g_mask[idx] = bits;
}

// ---------------------------------------------------------------------------
// fp32 -> fp16 hi/lo split (weights, elementwise)
// ---------------------------------------------------------------------------
__global__ void conv_split(const float* __restrict__ in, __half* __restrict__ hi,
                           __half* __restrict__ lo, int n) {
    for (int i = blockIdx.x * blockDim.x + threadIdx.x; i < n; i += gridDim.x * blockDim.x) {
        float v = in[i];
        __half h = __float2half_rn(v);
        hi[i] = h;
        lo[i] = __float2half_rn(v - __half2float(h));
    }
}

// x [B, K=768, N=16384] fp32 -> xT [B, N, K] fp16 single (transposed round)
__global__ void conv_xT(const float* __restrict__ x) {
    __shared__ float t[32][33];
    int bz = blockIdx.z;
    int n0 = blockIdx.x * 32, k0 = blockIdx.y * 32;
    int tx = threadIdx.x, ty = threadIdx.y;
    const float* xp = x + ((size_t)bz * DD + k0) * GP + n0;
    for (int i = ty; i < 32; i += 8) t[i][tx] = xp[(size_t)i * GP + tx];
    __syncthreads();
    for (int r = ty; r < 32; r += 8) {
        size_t o = ((size_t)bz * GP + n0 + r) * DD + k0 + tx;
        g_xT[o] = __float2half_rn(t[tx][r]);
    }
}

// ---------------------------------------------------------------------------
// Warp-MMA GEMM (R4 structure, fp16 2-product): C[bz] = A @ B[bz]^T (+ bias)
//   A : [Mtot, K] fp16 hi/lo (K-major), shared over batch (weights, split)
//   B^T: [NT, K]  fp16 single (K-major), per batch
// CTA 128x128 (blockIdx.x = N-block, as R4), 8 warps (2m x 4n), warp tile
// 64x32, K-chunk 32, 2 smem stages (30KB each, 80B padded rows), register
// double-buffer prefetch. 2 products per step: Ah*B + Al*B (exact in A;
// error = A * fp16-rounding(B) ~ 2.8e-4 RMS).
// ---------------------------------------------------------------------------
#define GOAH 0u
#define GOAL 10240u
#define GOB  20480u
#define GST  30720u

__global__ __launch_bounds__(256, 1) void gemm_mma(
    const __half* __restrict__ Ah, const __half* __restrict__ Al,
    const __half* __restrict__ B_,
    float* __restrict__ C, const float* __restrict__ bias, int Mtot)
{
    extern __shared__ char smem[];
    const int tid = threadIdx.x;
    const int wid = tid >> 5, lane = tid & 31;
    const int bz = blockIdx.z;
    const int col0 = blockIdx.x * 128;   // N block (fastest, as R4)
    const int row0 = blockIdx.y * 128;   // M block
    const __half* B = B_ + (size_t)bz * NT * KK;
    float* Cb = C + (size_t)bz * (size_t)Mtot * NT;

    const int warpM = (wid & 1) * 64;
    const int warpN = (wid >> 1) * 32;
    const uint32_t sb = smem_u32(smem);

    // per-thread load mapping: row = tid>>1, two 16B chunks at (tid&1)*32B
    const int lr = tid >> 1;
    const int lc = (tid & 1) * 2;
    const __half* pAh = Ah + (size_t)(row0 + lr) * KK + lc * 8;
    const __half* pAl = Al + (size_t)(row0 + lr) * KK + lc * 8;
    const __half* pB  = B  + (size_t)(col0 + lr) * KK + lc * 8;
    const uint32_t ss = lr * 80 + lc * 16;

    // ldmatrix lane roles
    const int t0 = lane & 7, sel = lane >> 3;
    const uint32_t a_lrow = (warpM + t0 + ((sel & 1) << 3)) * 80 + ((sel >> 1) << 4);
    const uint32_t b_lrow = (warpN + t0 + ((sel >> 1) << 3)) * 80 + ((sel & 1) << 4);

    float acc[4][4][4];
#pragma unroll
    for (int i = 0; i < 4; i++)
#pragma unroll
        for (int j = 0; j < 4; j++)
#pragma unroll
            for (int r = 0; r < 4; r++) acc[i][j][r] = 0.0f;

    // preload chunk 0
    uint4 pah[2], pal[2], pb[2];
#pragma unroll
    for (int u = 0; u < 2; u++) {
        pah[u] = *(const uint4*)(pAh + u * 8);
        pal[u] = *(const uint4*)(pAl + u * 8);
        pb[u]  = *(const uint4*)(pB  + u * 8);
    }
#pragma unroll
    for (int u = 0; u < 2; u++) {
        *(uint4*)(smem + GOAH + ss + u * 16) = pah[u];
        *(uint4*)(smem + GOAL + ss + u * 16) = pal[u];
        *(uint4*)(smem + GOB  + ss + u * 16) = pb[u];
    }
    __syncthreads();

    const int NCH = KK / 32;   // 24
    int buf = 0;
    for (int c = 0; c < NCH; c++) {
        if (c + 1 < NCH) {
            const size_t ko = (size_t)(c + 1) * 32;
#pragma unroll
            for (int u = 0; u < 2; u++) {
                pah[u] = *(const uint4*)(pAh + ko + u * 8);
                pal[u] = *(const uint4*)(pAl + ko + u * 8);
                pb[u]  = *(const uint4*)(pB  + ko + u * 8);
            }
        }
        const uint32_t so = sb + (uint32_t)buf * GST;
#pragma unroll
        for (int ks = 0; ks < 2; ks++) {
            uint32_t ah[4][4], al[4][4], bh[4][2];
#pragma unroll
            for (int mt = 0; mt < 4; mt++) {
                const uint32_t ad = so + a_lrow + mt * 16 * 80 + ks * 32;
                ldsm4(ah[mt][0], ah[mt][1], ah[mt][2], ah[mt][3], ad + GOAH);
                ldsm4(al[mt][0], al[mt][1], al[mt][2], al[mt][3], ad + GOAL);
            }
#pragma unroll
            for (int ntp = 0; ntp < 2; ntp++) {
                const uint32_t bd = so + b_lrow + ntp * 16 * 80 + ks * 32;
                ldsm4(bh[2 * ntp][0], bh[2 * ntp][1], bh[2 * ntp + 1][0],
                      bh[2 * ntp + 1][1], bd + GOB);
            }
#pragma unroll
            for (int mt = 0; mt < 4; mt++)
#pragma unroll
                for (int nt = 0; nt < 4; nt++) {
                    mma16816(acc[mt][nt], ah[mt], bh[nt]);
                    mma16816(acc[mt][nt], al[mt], bh[nt]);
                }
        }
        if (c + 1 < NCH) {
            const int nb = buf ^ 1;
            const uint32_t dst = (uint32_t)nb * GST + ss;
#pragma unroll
            for (int u = 0; u < 2; u++) {
                *(uint4*)(smem + GOAH + dst + u * 16) = pah[u];
                *(uint4*)(smem + GOAL + dst + u * 16) = pal[u];
                *(uint4*)(smem + GOB  + dst + u * 16) = pb[u];
            }
            __syncthreads();
            buf = nb;
        }
    }

    // epilogue: fragment -> gmem, bias by M-row
    const int gID = lane >> 2, tig = lane & 3;
#pragma unroll
    for (int mt = 0; mt < 4; mt++) {
#pragma unroll
        for (int half = 0; half < 2; half++) {
            const int row = row0 + warpM + mt * 16 + gID + half * 8;
            const float bv = bias ? __ldg(&bias[row]) : 0.0f;
            float* cp = Cb + (size_t)row * NT + col0 + warpN + tig * 2;
#pragma unroll
            for (int nt = 0; nt < 4; nt++) {
                float2 v = make_float2(acc[mt][nt][half * 2 + 0] + bv,
                                       acc[mt][nt][half * 2 + 1] + bv);
                *(float2*)(cp + nt * 8) = v;
            }
        }
    }
}

// ---------------------------------------------------------------------------
// Fused attention (R4 formulation): one CTA per (b, h, g). 256 threads =
// 256 query rows. K/V in 128KB smem ([hd][p] fp32). QK^T via packed f32x2;
// online softmax in exp2 domain. Output written as transposed fp16 for GEMM2.
// ---------------------------------------------------------------------------
__global__ __launch_bounds__(256, 1) void attn_kernel(const float* __restrict__ qkv)
{
    const int g = blockIdx.x, h = blockIdx.y, b = blockIdx.z;
    const int p = threadIdx.x;

    extern __shared__ float sm[];
    float* Ks = sm;              // [64][256]
    float* Vs = sm + 64 * 256;   // [64][256]

    const size_t plane = (size_t)GP;
    const float* gq = qkv + ((size_t)b * E3D + h * HD) * plane + (size_t)g * PP;
    const float* gk = gq + (size_t)DD * plane;
    const float* gv = gq + (size_t)(2 * DD) * plane;

    for (int idx = threadIdx.x; idx < 64 * 64; idx += 256) {
        int hd = idx >> 6;
        int p4 = (idx & 63) << 2;
        *(float4*)&Ks[hd * 256 + p4] = *(const float4*)&gk[(size_t)hd * plane + p4];
        *(float4*)&Vs[hd * 256 + p4] = *(const float4*)&gv[(size_t)hd * plane + p4];
    }

    const float CC = 0.18033688011112042f;  // (1/8) * log2(e)
    float q[HD];
#pragma unroll
    for (int d = 0; d < HD; d++) q[d] = gq[(size_t)d * plane + p] * CC;

    unsigned mbits[8];
    {
        const unsigned* mrow = g_mask + ((size_t)g * PP + p) * 8;
#pragma unroll
        for (int i = 0; i < 8; i++) mbits[i] = mrow[i];
    }

    __syncthreads();

    float m = -INFINITY, l = 0.0f;
    float o[HD];
#pragma unroll
    for (int d = 0; d < HD; d++) o[d] = 0.0f;

    const ull* K2 = (const ull*)Ks;
    const float4* V4 = (const float4*)Vs;

    for (int j4 = 0; j4 < 64; j4++) {
        ull s01 = 0ull, s23 = 0ull;
#pragma unroll
        for (int d = 0; d < HD; d++) {
            ull qq = pack2(q[d], q[d]);
            s01 = fma2(qq, K2[d * 128 + j4 * 2 + 0], s01);
            s23 = fma2(qq, K2[d * 128 + j4 * 2 + 1], s23);
        }
        float s0, s1, s2, s3;
        unpack2(s01, s0, s1);
        unpack2(s23, s2, s3);

        unsigned kp = (mbits[j4 >> 3] >> ((j4 & 7) << 2)) & 0xFu;
        if (!(kp & 1u)) s0 = -1e30f;
        if (!(kp & 2u)) s1 = -1e30f;
        if (!(kp & 4u)) s2 = -1e30f;
        if (!(kp & 8u)) s3 = -1e30f;

        float mx = fmaxf(fmaxf(s0, s1), fmaxf(s2, s3));
        if (mx > m) {
            float al = fexp2(m - mx);
            l *= al;
#pragma unroll
            for (int d = 0; d < HD; d++) o[d] *= al;
            m = mx;
        }
        float w0 = fexp2(s0 - m);
        float w1 = fexp2(s1 - m);
        float w2 = fexp2(s2 - m);
        float w3 = fexp2(s3 - m);
        l += (w0 + w1) + (w2 + w3);
#pragma unroll
        for (int d = 0; d < HD; d++) {
            float4 vv = V4[d * 64 + j4];
            o[d] += (w0 * vv.x + w1 * vv.y) + (w2 * vv.z + w3 * vv.w);
        }
    }

    // epilogue: normalize, fp16 round, transposed write
    const float inv = 1.0f / l;
    const size_t orow = ((size_t)b * GP + (size_t)g * PP + p) * DD + h * HD;
#pragma unroll
    for (int d = 0; d < HD; d += 2) {
        __half2 hv = __floats2half2_rn(o[d] * inv, o[d + 1] * inv);
        *(__half2*)(&g_aT[orow + d]) = hv;
    }
}

// ---------------------------------------------------------------------------
extern "C" void kernel_launch(void* const* d_in, const int* in_sizes, int n_in,
                              void* d_out, int out_size)
{
    const float* x      = (const float*)d_in[0];
    const void*  mask   = d_in[1];
    const float* w_qkv  = (const float*)d_in[2];
    const float* w_proj = (const float*)d_in[3];
    const float* b_proj = (const float*)d_in[4];
    float*       out    = (float*)d_out;

    float *qkvbuf = nullptr;
    __half *xt, *at, *wqh, *wql, *wph, *wpl;
    cudaGetSymbolAddress((void**)&qkvbuf, g_qkv);
    cudaGetSymbolAddress((void**)&xt, g_xT);
    cudaGetSymbolAddress((void**)&at, g_aT);
    cudaGetSymbolAddress((void**)&wqh, g_wq_hi);
    cudaGetSymbolAddress((void**)&wql, g_wq_lo);
    cudaGetSymbolAddress((void**)&wph, g_wp_hi);
    cudaGetSymbolAddress((void**)&wpl, g_wp_lo);

    // 0) mask dtype detection + bit packing
    detect_mask_dtype<<<1, 32>>>((const unsigned*)mask);
    pack_mask<<<(GG * PP * 8 + 255) / 256, 256>>>(mask);

    // 1) fp16 conversions: weights hi/lo split + transposed x (single)
    conv_split<<<1024, 256>>>(w_qkv, wqh, wql, E3D * DD);
    conv_split<<<1024, 256>>>(w_proj, wph, wpl, DD * DD);
    conv_xT<<<dim3(GP / 32, DD / 32, BB), dim3(32, 8)>>>(x);

    const int GEMM_SMEM = 2 * 30720;         // 60KB, 2 stages
    const int ATTN_SMEM = 131072;            // 128KB K+V
    cudaFuncSetAttribute(gemm_mma, cudaFuncAttributeMaxDynamicSharedMemorySize, GEMM_SMEM);
    cudaFuncSetAttribute(attn_kernel, cudaFuncAttributeMaxDynamicSharedMemorySize, ATTN_SMEM);

    // 2) QKV projection: [2304 x 768] @ [768 x 16384] per batch (R4 grid order)
    gemm_mma<<<dim3(NT / 128, E3D / 128, BB), 256, GEMM_SMEM>>>(
        wqh, wql, xt, qkvbuf, nullptr, E3D);

    // 3) fused masked attention per (b, h, g) -> transposed fp16 output
    attn_kernel<<<dim3(GG, HH, BB), 256, ATTN_SMEM>>>(qkvbuf);

    // 4) output projection + bias
    gemm_mma<<<dim3(NT / 128, DD / 128, BB), 256, GEMM_SMEM>>>(
        wph, wpl, at, out, b_proj, DD);
}

// round 10
// speedup vs baseline: 1.3762x; 1.1473x over previous
#include <cuda_runtime.h>
#include <cuda_fp16.h>
#include <math.h>
#include <stdint.h>

// Problem constants
#define BB 4
#define DD 768
#define GG 64
#define PP 256
#define HH 12
#define HD 64
#define GP (GG * PP)            // 16384
#define E3D (3 * DD)            // 2304
#define KK 768                  // K dim of both GEMMs
#define NT GP                   // N total of both GEMMs

// ---------------- scratch (allocation-free rule: __device__ globals) -------
__device__ __align__(256) float g_qkv[(size_t)BB * E3D * GP];   // [B, 3D, G*P]
__device__ __align__(256) __half g_xT[(size_t)BB * GP * DD];    // x^T [B,N,K] fp16
__device__ __align__(256) __half g_aT[(size_t)BB * GP * DD];    // att^T fp16
__device__ __align__(256) __half g_wq_hi[(size_t)E3D * DD];
__device__ __align__(256) __half g_wq_lo[(size_t)E3D * DD];
__device__ __align__(256) __half g_wp_hi[(size_t)DD * DD];
__device__ __align__(256) __half g_wp_lo[(size_t)DD * DD];
__device__ unsigned g_mask[(size_t)GG * PP * 8];   // packed keep-bits per (g,p)
__device__ int g_mask_dtype;                       // 0=u8,1=i32,2=f32,3=bf16

typedef unsigned long long ull;

// ---------------- small PTX helpers ----------------------------------------
__device__ __forceinline__ ull pack2(float x, float y) {
    ull r; asm("mov.b64 %0, {%1, %2};" : "=l"(r) : "f"(x), "f"(y)); return r;
}
__device__ __forceinline__ void unpack2(ull v, float& x, float& y) {
    asm("mov.b64 {%0, %1}, %2;" : "=f"(x), "=f"(y) : "l"(v));
}
__device__ __forceinline__ ull fma2(ull a, ull b, ull c) {
    ull d; asm("fma.rn.f32x2 %0, %1, %2, %3;" : "=l"(d) : "l"(a), "l"(b), "l"(c));
    return d;
}
__device__ __forceinline__ uint32_t smem_u32(const void* p) {
    uint32_t a;
    asm("{ .reg .u64 t; cvta.to.shared.u64 t, %1; cvt.u32.u64 %0, t; }"
        : "=r"(a) : "l"(p));
    return a;
}
__device__ __forceinline__ void ldsm4(uint32_t& r0, uint32_t& r1, uint32_t& r2,
                                      uint32_t& r3, uint32_t addr) {
    asm volatile("ldmatrix.sync.aligned.m8n8.x4.shared.b16 {%0,%1,%2,%3}, [%4];"
                 : "=r"(r0), "=r"(r1), "=r"(r2), "=r"(r3) : "r"(addr));
}
__device__ __forceinline__ void mma16816(float* c, const uint32_t* a, const uint32_t* b) {
    asm volatile(
        "mma.sync.aligned.m16n8k16.row.col.f32.f16.f16.f32 "
        "{%0,%1,%2,%3}, {%4,%5,%6,%7}, {%8,%9}, {%0,%1,%2,%3};"
        : "+f"(c[0]), "+f"(c[1]), "+f"(c[2]), "+f"(c[3])
        : "r"(a[0]), "r"(a[1]), "r"(a[2]), "r"(a[3]), "r"(b[0]), "r"(b[1]));
}

// Fast exp2 entirely on FMA/ALU pipes (magic-constant round, no cvt pipe).
__device__ __forceinline__ float fexp2(float t) {
    t = fmaxf(t, -120.0f);
    float r = t + 12582912.0f;             // round-to-nearest-int in mantissa
    float f = t - (r - 12582912.0f);       // [-0.5, 0.5]
    int   sc = (__float_as_int(r) - 0x4B3FFF81) << 23;  // (n+127)<<23
    float p = 1.5403530e-4f;
    p = fmaf(p, f, 1.3333558e-3f);
    p = fmaf(p, f, 9.6181291e-3f);
    p = fmaf(p, f, 5.5504109e-2f);
    p = fmaf(p, f, 2.4022651e-1f);
    p = fmaf(p, f, 6.9314718e-1f);
    p = fmaf(p, f, 1.0f);
    return p * __int_as_float(sc);
}

// ---------------------------------------------------------------------------
// Mask dtype detection + packing
// ---------------------------------------------------------------------------
__global__ void detect_mask_dtype(const unsigned* __restrict__ m) {
    if (threadIdx.x != 0 || blockIdx.x != 0) return;
    int dt = 1;
    for (int i = 0; i < 1024; i++) {
        unsigned w = m[i];
        if (w == 0x3F800000u) { dt = 2; break; }
        if ((w & 0xFFFFu) == 0x3F80u || (w >> 16) == 0x3F80u) { dt = 3; break; }
        if (w > 1u) { dt = 0; break; }
    }
    g_mask_dtype = dt;
}

__global__ void pack_mask(const void* __restrict__ mraw) {
    int idx = blockIdx.x * blockDim.x + threadIdx.x;
    if (idx >= GG * PP * 8) return;
    int row = idx >> 3, w = idx & 7;
    int dt = g_mask_dtype;
    size_t base = (size_t)row * PP + w * 32;
    unsigned bits = 0;
    for (int t = 0; t < 32; t++) {
        bool keep;
        if (dt == 0)      keep = ((const unsigned char*)mraw)[base + t] != 0;
        else if (dt == 1) keep = ((const int*)mraw)[base + t] != 0;
        else if (dt == 2) keep = ((const float*)mraw)[base + t] != 0.0f;
        else              keep = ((const unsigned short*)mraw)[base + t] != 0;
        if (keep) bits |= 1u << t;
    }
    g_mask[idx] = bits;
}

// ---------------------------------------------------------------------------
// fp32 -> fp16 hi/lo split (weights, elementwise)
// ---------------------------------------------------------------------------
__global__ void conv_split(const float* __restrict__ in, __half* __restrict__ hi,
                           __half* __restrict__ lo, int n) {
    for (int i = blockIdx.x * blockDim.x + threadIdx.x; i < n; i += gridDim.x * blockDim.x) {
        float v = in[i];
        __half h = __float2half_rn(v);
        hi[i] = h;
        lo[i] = __float2half_rn(v - __half2float(h));
    }
}

// x [B, K=768, N=16384] fp32 -> xT [B, N, K] fp16 single (transposed round)
__global__ void conv_xT(const float* __restrict__ x) {
    __shared__ float t[32][33];
    int bz = blockIdx.z;
    int n0 = blockIdx.x * 32, k0 = blockIdx.y * 32;
    int tx = threadIdx.x, ty = threadIdx.y;
    const float* xp = x + ((size_t)bz * DD + k0) * GP + n0;
    for (int i = ty; i < 32; i += 8) t[i][tx] = xp[(size_t)i * GP + tx];
    __syncthreads();
    for (int r = ty; r < 32; r += 8) {
        size_t o = ((size_t)bz * GP + n0 + r) * DD + k0 + tx;
        g_xT[o] = __float2half_rn(t[tx][r]);
    }
}

// ---------------------------------------------------------------------------
// Warp-MMA GEMM (R8 structure), NPROD = 1 (pure fp16) or 2 (compensated A):
//   C[bz] = A @ B[bz]^T (+ bias)
//   A : [Mtot, K] fp16 (hi [, lo]) K-major, shared over batch
//   B^T: [NT, K] fp16 single K-major, per batch
// CTA 128x128, 8 warps (2m x 4n), warp tile 64x32, K-chunk 32, 2 smem stages
// (80B padded rows), register double-buffer prefetch.
// ---------------------------------------------------------------------------
template <int NPROD>
__global__ __launch_bounds__(256, 1) void gemm_mma(
    const __half* __restrict__ Ah, const __half* __restrict__ Al,
    const __half* __restrict__ B_,
    float* __restrict__ C, const float* __restrict__ bias, int Mtot)
{
    extern __shared__ char smem[];
    constexpr uint32_t GOAH = 0u;
    constexpr uint32_t GOAL = 10240u;                        // only if NPROD==2
    constexpr uint32_t GOB  = (NPROD == 2) ? 20480u : 10240u;
    constexpr uint32_t GST  = GOB + 10240u;                  // stage stride

    const int tid = threadIdx.x;
    const int wid = tid >> 5, lane = tid & 31;
    const int bz = blockIdx.z;
    const int col0 = blockIdx.x * 128;   // N block (fastest)
    const int row0 = blockIdx.y * 128;   // M block
    const __half* B = B_ + (size_t)bz * NT * KK;
    float* Cb = C + (size_t)bz * (size_t)Mtot * NT;

    const int warpM = (wid & 1) * 64;
    const int warpN = (wid >> 1) * 32;
    const uint32_t sb = smem_u32(smem);

    // per-thread load mapping: row = tid>>1, two 16B chunks at (tid&1)*32B
    const int lr = tid >> 1;
    const int lc = (tid & 1) * 2;
    const __half* pAh = Ah + (size_t)(row0 + lr) * KK + lc * 8;
    const __half* pAl = (NPROD == 2) ? (Al + (size_t)(row0 + lr) * KK + lc * 8) : nullptr;
    const __half* pB  = B  + (size_t)(col0 + lr) * KK + lc * 8;
    const uint32_t ss = lr * 80 + lc * 16;

    // ldmatrix lane roles
    const int t0 = lane & 7, sel = lane >> 3;
    const uint32_t a_lrow = (warpM + t0 + ((sel & 1) << 3)) * 80 + ((sel >> 1) << 4);
    const uint32_t b_lrow = (warpN + t0 + ((sel >> 1) << 3)) * 80 + ((sel & 1) << 4);

    float acc[4][4][4];
#pragma unroll
    for (int i = 0; i < 4; i++)
#pragma unroll
        for (int j = 0; j < 4; j++)
#pragma unroll
            for (int r = 0; r < 4; r++) acc[i][j][r] = 0.0f;

    // preload chunk 0
    uint4 pah[2], pal[2], pb[2];
#pragma unroll
    for (int u = 0; u < 2; u++) {
        pah[u] = *(const uint4*)(pAh + u * 8);
        if (NPROD == 2) pal[u] = *(const uint4*)(pAl + u * 8);
        pb[u]  = *(const uint4*)(pB  + u * 8);
    }
#pragma unroll
    for (int u = 0; u < 2; u++) {
        *(uint4*)(smem + GOAH + ss + u * 16) = pah[u];
        if (NPROD == 2) *(uint4*)(smem + GOAL + ss + u * 16) = pal[u];
        *(uint4*)(smem + GOB  + ss + u * 16) = pb[u];
    }
    __syncthreads();

    const int NCH = KK / 32;   // 24
    int buf = 0;
    for (int c = 0; c < NCH; c++) {
        if (c + 1 < NCH) {
            const size_t ko = (size_t)(c + 1) * 32;
#pragma unroll
            for (int u = 0; u < 2; u++) {
                pah[u] = *(const uint4*)(pAh + ko + u * 8);
                if (NPROD == 2) pal[u] = *(const uint4*)(pAl + ko + u * 8);
                pb[u]  = *(const uint4*)(pB  + ko + u * 8);
            }
        }
        const uint32_t so = sb + (uint32_t)buf * GST;
#pragma unroll
        for (int ks = 0; ks < 2; ks++) {
            uint32_t ah[4][4], al[4][4], bh[4][2];
#pragma unroll
            for (int mt = 0; mt < 4; mt++) {
                const uint32_t ad = so + a_lrow + mt * 16 * 80 + ks * 32;
                ldsm4(ah[mt][0], ah[mt][1], ah[mt][2], ah[mt][3], ad + GOAH);
                if (NPROD == 2)
                    ldsm4(al[mt][0], al[mt][1], al[mt][2], al[mt][3], ad + GOAL);
            }
#pragma unroll
            for (int ntp = 0; ntp < 2; ntp++) {
                const uint32_t bd = so + b_lrow + ntp * 16 * 80 + ks * 32;
                ldsm4(bh[2 * ntp][0], bh[2 * ntp][1], bh[2 * ntp + 1][0],
                      bh[2 * ntp + 1][1], bd + GOB);
            }
#pragma unroll
            for (int mt = 0; mt < 4; mt++)
#pragma unroll
                for (int nt = 0; nt < 4; nt++) {
                    mma16816(acc[mt][nt], ah[mt], bh[nt]);
                    if (NPROD == 2) mma16816(acc[mt][nt], al[mt], bh[nt]);
                }
        }
        if (c + 1 < NCH) {
            const int nb = buf ^ 1;
            const uint32_t dst = (uint32_t)nb * GST + ss;
#pragma unroll
            for (int u = 0; u < 2; u++) {
                *(uint4*)(smem + GOAH + dst + u * 16) = pah[u];
                if (NPROD == 2) *(uint4*)(smem + GOAL + dst + u * 16) = pal[u];
                *(uint4*)(smem + GOB  + dst + u * 16) = pb[u];
            }
            __syncthreads();
            buf = nb;
        }
    }

    // epilogue: fragment -> gmem, bias by M-row
    const int gID = lane >> 2, tig = lane & 3;
#pragma unroll
    for (int mt = 0; mt < 4; mt++) {
#pragma unroll
        for (int half = 0; half < 2; half++) {
            const int row = row0 + warpM + mt * 16 + gID + half * 8;
            const float bv = bias ? __ldg(&bias[row]) : 0.0f;
            float* cp = Cb + (size_t)row * NT + col0 + warpN + tig * 2;
#pragma unroll
            for (int nt = 0; nt < 4; nt++) {
                float2 v = make_float2(acc[mt][nt][half * 2 + 0] + bv,
                                       acc[mt][nt][half * 2 + 1] + bv);
                *(float2*)(cp + nt * 8) = v;
            }
        }
    }
}

// ---------------------------------------------------------------------------
// Fused attention (R4 formulation): one CTA per (b, h, g). 256 threads =
// 256 query rows. K/V in 128KB smem ([hd][p] fp32). QK^T via packed f32x2;
// online softmax in exp2 domain. Output written as transposed fp16 for GEMM2.
// ---------------------------------------------------------------------------
__global__ __launch_bounds__(256, 1) void attn_kernel(const float* __restrict__ qkv)
{
    const int g = blockIdx.x, h = blockIdx.y, b = blockIdx.z;
    const int p = threadIdx.x;

    extern __shared__ float sm[];
    float* Ks = sm;              // [64][256]
    float* Vs = sm + 64 * 256;   // [64][256]

    const size_t plane = (size_t)GP;
    const float* gq = qkv + ((size_t)b * E3D + h * HD) * plane + (size_t)g * PP;
    const float* gk = gq + (size_t)DD * plane;
    const float* gv = gq + (size_t)(2 * DD) * plane;

    for (int idx = threadIdx.x; idx < 64 * 64; idx += 256) {
        int hd = idx >> 6;
        int p4 = (idx & 63) << 2;
        *(float4*)&Ks[hd * 256 + p4] = *(const float4*)&gk[(size_t)hd * plane + p4];
        *(float4*)&Vs[hd * 256 + p4] = *(const float4*)&gv[(size_t)hd * plane + p4];
    }

    const float CC = 0.18033688011112042f;  // (1/8) * log2(e)
    float q[HD];
#pragma unroll
    for (int d = 0; d < HD; d++) q[d] = gq[(size_t)d * plane + p] * CC;

    unsigned mbits[8];
    {
        const unsigned* mrow = g_mask + ((size_t)g * PP + p) * 8;
#pragma unroll
        for (int i = 0; i < 8; i++) mbits[i] = mrow[i];
    }

    __syncthreads();

    float m = -INFINITY, l = 0.0f;
    float o[HD];
#pragma unroll
    for (int d = 0; d < HD; d++) o[d] = 0.0f;

    const ull* K2 = (const ull*)Ks;
    const float4* V4 = (const float4*)Vs;

    for (int j4 = 0; j4 < 64; j4++) {
        ull s01 = 0ull, s23 = 0ull;
#pragma unroll
        for (int d = 0; d < HD; d++) {
            ull qq = pack2(q[d], q[d]);
            s01 = fma2(qq, K2[d * 128 + j4 * 2 + 0], s01);
            s23 = fma2(qq, K2[d * 128 + j4 * 2 + 1], s23);
        }
        float s0, s1, s2, s3;
        unpack2(s01, s0, s1);
        unpack2(s23, s2, s3);

        unsigned kp = (mbits[j4 >> 3] >> ((j4 & 7) << 2)) & 0xFu;
        if (!(kp & 1u)) s0 = -1e30f;
        if (!(kp & 2u)) s1 = -1e30f;
        if (!(kp & 4u)) s2 = -1e30f;
        if (!(kp & 8u)) s3 = -1e30f;

        float mx = fmaxf(fmaxf(s0, s1), fmaxf(s2, s3));
        if (mx > m) {
            float al = fexp2(m - mx);
            l *= al;
#pragma unroll
            for (int d = 0; d < HD; d++) o[d] *= al;
            m = mx;
        }
        float w0 = fexp2(s0 - m);
        float w1 = fexp2(s1 - m);
        float w2 = fexp2(s2 - m);
        float w3 = fexp2(s3 - m);
        l += (w0 + w1) + (w2 + w3);
#pragma unroll
        for (int d = 0; d < HD; d++) {
            float4 vv = V4[d * 64 + j4];
            o[d] += (w0 * vv.x + w1 * vv.y) + (w2 * vv.z + w3 * vv.w);
        }
    }

    // epilogue: normalize, fp16 round, transposed write
    const float inv = 1.0f / l;
    const size_t orow = ((size_t)b * GP + (size_t)g * PP + p) * DD + h * HD;
#pragma unroll
    for (int d = 0; d < HD; d += 2) {
        __half2 hv = __floats2half2_rn(o[d] * inv, o[d + 1] * inv);
        *(__half2*)(&g_aT[orow + d]) = hv;
    }
}

// ---------------------------------------------------------------------------
extern "C" void kernel_launch(void* const* d_in, const int* in_sizes, int n_in,
                              void* d_out, int out_size)
{
    const float* x      = (const float*)d_in[0];
    const void*  mask   = d_in[1];
    const float* w_qkv  = (const float*)d_in[2];
    const float* w_proj = (const float*)d_in[3];
    const float* b_proj = (const float*)d_in[4];
    float*       out    = (float*)d_out;

    float *qkvbuf = nullptr;
    __half *xt, *at, *wqh, *wql, *wph, *wpl;
    cudaGetSymbolAddress((void**)&qkvbuf, g_qkv);
    cudaGetSymbolAddress((void**)&xt, g_xT);
    cudaGetSymbolAddress((void**)&at, g_aT);
    cudaGetSymbolAddress((void**)&wqh, g_wq_hi);
    cudaGetSymbolAddress((void**)&wql, g_wq_lo);
    cudaGetSymbolAddress((void**)&wph, g_wp_hi);
    cudaGetSymbolAddress((void**)&wpl, g_wp_lo);

    // 0) mask dtype detection + bit packing
    detect_mask_dtype<<<1, 32>>>((const unsigned*)mask);
    pack_mask<<<(GG * PP * 8 + 255) / 256, 256>>>(mask);

    // 1) fp16 conversions: weights (hi/lo for proj; hi used for qkv) + x^T
    conv_split<<<1024, 256>>>(w_qkv, wqh, wql, E3D * DD);
    conv_split<<<1024, 256>>>(w_proj, wph, wpl, DD * DD);
    conv_xT<<<dim3(GP / 32, DD / 32, BB), dim3(32, 8)>>>(x);

    const int GEMM1_SMEM = 2 * 20480;        // 40KB: A + B, 2 stages
    const int GEMM2_SMEM = 2 * 30720;        // 60KB: Ah + Al + B, 2 stages
    const int ATTN_SMEM  = 131072;           // 128KB K+V
    cudaFuncSetAttribute(gemm_mma<1>, cudaFuncAttributeMaxDynamicSharedMemorySize, GEMM1_SMEM);
    cudaFuncSetAttribute(gemm_mma<2>, cudaFuncAttributeMaxDynamicSharedMemorySize, GEMM2_SMEM);
    cudaFuncSetAttribute(attn_kernel, cudaFuncAttributeMaxDynamicSharedMemorySize, ATTN_SMEM);

    // 2) QKV projection, pure fp16 1-product: [2304x768] @ [768x16384] per batch
    gemm_mma<1><<<dim3(NT / 128, E3D / 128, BB), 256, GEMM1_SMEM>>>(
        wqh, nullptr, xt, qkvbuf, nullptr, E3D);

    // 3) fused masked attention per (b, h, g) -> transposed fp16 output
    attn_kernel<<<dim3(GG, HH, BB), 256, ATTN_SMEM>>>(qkvbuf);

    // 4) output projection + bias, compensated 2-product (weights exact)
    gemm_mma<2><<<dim3(NT / 128, DD / 128, BB), 256, GEMM2_SMEM>>>(
        wph, wpl, at, out, b_proj, DD);
}

// round 12
// speedup vs baseline: 2.1296x; 1.5474x over previous
#include <cuda_runtime.h>
#include <cuda_fp16.h>
#include <math.h>
#include <stdint.h>

// Problem constants
#define BB 4
#define DD 768
#define GG 64
#define PP 256
#define HH 12
#define HD 64
#define GP (GG * PP)            // 16384
#define E3D (3 * DD)            // 2304
#define KK 768                  // K dim of both GEMMs
#define NT GP                   // N total of both GEMMs

// ---------------- scratch (allocation-free rule: __device__ globals) -------
__device__ __align__(256) __half g_qkv[(size_t)BB * E3D * GP];  // fp16 qkv
__device__ __align__(256) __half g_xT[(size_t)BB * GP * DD];    // x^T [B,N,K]
__device__ __align__(256) __half g_aT[(size_t)BB * GP * DD];    // att^T fp16
__device__ __align__(256) __half g_wq_hi[(size_t)E3D * DD];
__device__ __align__(256) __half g_wq_lo[(size_t)E3D * DD];
__device__ __align__(256) __half g_wp_hi[(size_t)DD * DD];
__device__ __align__(256) __half g_wp_lo[(size_t)DD * DD];
__device__ unsigned g_mask[(size_t)GG * PP * 8];   // packed keep-bits per (g,p)
__device__ int g_mask_dtype;                       // 0=u8,1=i32,2=f32,3=bf16

typedef unsigned long long ull;

// ---------------- small PTX helpers ----------------------------------------
__device__ __forceinline__ uint32_t smem_u32(const void* p) {
    uint32_t a;
    asm("{ .reg .u64 t; cvta.to.shared.u64 t, %1; cvt.u32.u64 %0, t; }"
        : "=r"(a) : "l"(p));
    return a;
}
__device__ __forceinline__ void ldsm4(uint32_t& r0, uint32_t& r1, uint32_t& r2,
                                      uint32_t& r3, uint32_t addr) {
    asm volatile("ldmatrix.sync.aligned.m8n8.x4.shared.b16 {%0,%1,%2,%3}, [%4];"
                 : "=r"(r0), "=r"(r1), "=r"(r2), "=r"(r3) : "r"(addr));
}
__device__ __forceinline__ void mma16816(float* c, const uint32_t* a, const uint32_t* b) {
    asm volatile(
        "mma.sync.aligned.m16n8k16.row.col.f32.f16.f16.f32 "
        "{%0,%1,%2,%3}, {%4,%5,%6,%7}, {%8,%9}, {%0,%1,%2,%3};"
        : "+f"(c[0]), "+f"(c[1]), "+f"(c[2]), "+f"(c[3])
        : "r"(a[0]), "r"(a[1]), "r"(a[2]), "r"(a[3]), "r"(b[0]), "r"(b[1]));
}
__device__ __forceinline__ uint32_t h2pack(float a, float b) {
    __half2 h = __floats2half2_rn(a, b);
    return *(uint32_t*)&h;
}

// Fast exp2 entirely on FMA/ALU pipes (magic-constant round, no cvt pipe).
__device__ __forceinline__ float fexp2(float t) {
    t = fmaxf(t, -120.0f);
    float r = t + 12582912.0f;             // round-to-nearest-int in mantissa
    float f = t - (r - 12582912.0f);       // [-0.5, 0.5]
    int   sc = (__float_as_int(r) - 0x4B3FFF81) << 23;  // (n+127)<<23
    float p = 1.5403530e-4f;
    p = fmaf(p, f, 1.3333558e-3f);
    p = fmaf(p, f, 9.6181291e-3f);
    p = fmaf(p, f, 5.5504109e-2f);
    p = fmaf(p, f, 2.4022651e-1f);
    p = fmaf(p, f, 6.9314718e-1f);
    p = fmaf(p, f, 1.0f);
    return p * __int_as_float(sc);
}

// ---------------------------------------------------------------------------
// Mask dtype detection + packing
// ---------------------------------------------------------------------------
__global__ void detect_mask_dtype(const unsigned* __restrict__ m) {
    if (threadIdx.x != 0 || blockIdx.x != 0) return;
    int dt = 1;
    for (int i = 0; i < 1024; i++) {
        unsigned w = m[i];
        if (w == 0x3F800000u) { dt = 2; break; }
        if ((w & 0xFFFFu) == 0x3F80u || (w >> 16) == 0x3F80u) { dt = 3; break; }
        if (w > 1u) { dt = 0; break; }
    }
    g_mask_dtype = dt;
}

__global__ void pack_mask(const void* __restrict__ mraw) {
    int idx = blockIdx.x * blockDim.x + threadIdx.x;
    if (idx >= GG * PP * 8) return;
    int row = idx >> 3, w = idx & 7;
    int dt = g_mask_dtype;
    size_t base = (size_t)row * PP + w * 32;
    unsigned bits = 0;
    for (int t = 0; t < 32; t++) {
        bool keep;
        if (dt == 0)      keep = ((const unsigned char*)mraw)[base + t] != 0;
        else if (dt == 1) keep = ((const int*)mraw)[base + t] != 0;
        else if (dt == 2) keep = ((const float*)mraw)[base + t] != 0.0f;
        else              keep = ((const unsigned short*)mraw)[base + t] != 0;
        if (keep) bits |= 1u << t;
    }
    g_mask[idx] = bits;
}

// ---------------------------------------------------------------------------
// fp32 -> fp16 hi/lo split (weights, elementwise)
// ---------------------------------------------------------------------------
__global__ void conv_split(const float* __restrict__ in, __half* __restrict__ hi,
                           __half* __restrict__ lo, int n) {
    for (int i = blockIdx.x * blockDim.x + threadIdx.x; i < n; i += gridDim.x * blockDim.x) {
        float v = in[i];
        __half h = __float2half_rn(v);
        hi[i] = h;
        lo[i] = __float2half_rn(v - __half2float(h));
    }
}

// x [B, K=768, N=16384] fp32 -> xT [B, N, K] fp16 single (transposed round)
__global__ void conv_xT(const float* __restrict__ x) {
    __shared__ float t[32][33];
    int bz = blockIdx.z;
    int n0 = blockIdx.x * 32, k0 = blockIdx.y * 32;
    int tx = threadIdx.x, ty = threadIdx.y;
    const float* xp = x + ((size_t)bz * DD + k0) * GP + n0;
    for (int i = ty; i < 32; i += 8) t[i][tx] = xp[(size_t)i * GP + tx];
    __syncthreads();
    for (int r = ty; r < 32; r += 8) {
        size_t o = ((size_t)bz * GP + n0 + r) * DD + k0 + tx;
        g_xT[o] = __float2half_rn(t[tx][r]);
    }
}

// ---------------------------------------------------------------------------
// Warp-MMA GEMM (R9 structure), NPROD = 1 or 2, output type OT (float/half):
//   C[bz] = A @ B[bz]^T (+ bias)
// ---------------------------------------------------------------------------
template <int NPROD, typename OT>
__global__ __launch_bounds__(256, 1) void gemm_mma(
    const __half* __restrict__ Ah, const __half* __restrict__ Al,
    const __half* __restrict__ B_,
    OT* __restrict__ C, const float* __restrict__ bias, int Mtot)
{
    extern __shared__ char smem[];
    constexpr uint32_t GOAH = 0u;
    constexpr uint32_t GOAL = 10240u;                        // only if NPROD==2
    constexpr uint32_t GOB  = (NPROD == 2) ? 20480u : 10240u;
    constexpr uint32_t GST  = GOB + 10240u;                  // stage stride

    const int tid = threadIdx.x;
    const int wid = tid >> 5, lane = tid & 31;
    const int bz = blockIdx.z;
    const int col0 = blockIdx.x * 128;   // N block (fastest)
    const int row0 = blockIdx.y * 128;   // M block
    const __half* B = B_ + (size_t)bz * NT * KK;
    OT* Cb = C + (size_t)bz * (size_t)Mtot * NT;

    const int warpM = (wid & 1) * 64;
    const int warpN = (wid >> 1) * 32;
    const uint32_t sb = smem_u32(smem);

    const int lr = tid >> 1;
    const int lc = (tid & 1) * 2;
    const __half* pAh = Ah + (size_t)(row0 + lr) * KK + lc * 8;
    const __half* pAl = (NPROD == 2) ? (Al + (size_t)(row0 + lr) * KK + lc * 8) : nullptr;
    const __half* pB  = B  + (size_t)(col0 + lr) * KK + lc * 8;
    const uint32_t ss = lr * 80 + lc * 16;

    const int t0 = lane & 7, sel = lane >> 3;
    const uint32_t a_lrow = (warpM + t0 + ((sel & 1) << 3)) * 80 + ((sel >> 1) << 4);
    const uint32_t b_lrow = (warpN + t0 + ((sel >> 1) << 3)) * 80 + ((sel & 1) << 4);

    float acc[4][4][4];
#pragma unroll
    for (int i = 0; i < 4; i++)
#pragma unroll
        for (int j = 0; j < 4; j++)
#pragma unroll
            for (int r = 0; r < 4; r++) acc[i][j][r] = 0.0f;

    uint4 pah[2], pal[2], pb[2];
#pragma unroll
    for (int u = 0; u < 2; u++) {
        pah[u] = *(const uint4*)(pAh + u * 8);
        if (NPROD == 2) pal[u] = *(const uint4*)(pAl + u * 8);
        pb[u]  = *(const uint4*)(pB  + u * 8);
    }
#pragma unroll
    for (int u = 0; u < 2; u++) {
        *(uint4*)(smem + GOAH + ss + u * 16) = pah[u];
        if (NPROD == 2) *(uint4*)(smem + GOAL + ss + u * 16) = pal[u];
        *(uint4*)(smem + GOB  + ss + u * 16) = pb[u];
    }
    __syncthreads();

    const int NCH = KK / 32;   // 24
    int buf = 0;
    for (int c = 0; c < NCH; c++) {
        if (c + 1 < NCH) {
            const size_t ko = (size_t)(c + 1) * 32;
#pragma unroll
            for (int u = 0; u < 2; u++) {
                pah[u] = *(const uint4*)(pAh + ko + u * 8);
                if (NPROD == 2) pal[u] = *(const uint4*)(pAl + ko + u * 8);
                pb[u]  = *(const uint4*)(pB  + ko + u * 8);
            }
        }
        const uint32_t so = sb + (uint32_t)buf * GST;
#pragma unroll
        for (int ks = 0; ks < 2; ks++) {
            uint32_t ah[4][4], al[4][4], bh[4][2];
#pragma unroll
            for (int mt = 0; mt < 4; mt++) {
                const uint32_t ad = so + a_lrow + mt * 16 * 80 + ks * 32;
                ldsm4(ah[mt][0], ah[mt][1], ah[mt][2], ah[mt][3], ad + GOAH);
                if (NPROD == 2)
                    ldsm4(al[mt][0], al[mt][1], al[mt][2], al[mt][3], ad + GOAL);
            }
#pragma unroll
            for (int ntp = 0; ntp < 2; ntp++) {
                const uint32_t bd = so + b_lrow + ntp * 16 * 80 + ks * 32;
                ldsm4(bh[2 * ntp][0], bh[2 * ntp][1], bh[2 * ntp + 1][0],
                      bh[2 * ntp + 1][1], bd + GOB);
            }
#pragma unroll
            for (int mt = 0; mt < 4; mt++)
#pragma unroll
                for (int nt = 0; nt < 4; nt++) {
                    mma16816(acc[mt][nt], ah[mt], bh[nt]);
                    if (NPROD == 2) mma16816(acc[mt][nt], al[mt], bh[nt]);
                }
        }
        if (c + 1 < NCH) {
            const int nb = buf ^ 1;
            const uint32_t dst = (uint32_t)nb * GST + ss;
#pragma unroll
            for (int u = 0; u < 2; u++) {
                *(uint4*)(smem + GOAH + dst + u * 16) = pah[u];
                if (NPROD == 2) *(uint4*)(smem + GOAL + dst + u * 16) = pal[u];
                *(uint4*)(smem + GOB  + dst + u * 16) = pb[u];
            }
            __syncthreads();
            buf = nb;
        }
    }

    // epilogue: fragment -> gmem (float2 or half2), bias by M-row
    const int gID = lane >> 2, tig = lane & 3;
#pragma unroll
    for (int mt = 0; mt < 4; mt++) {
#pragma unroll
        for (int half = 0; half < 2; half++) {
            const int row = row0 + warpM + mt * 16 + gID + half * 8;
            const float bv = bias ? __ldg(&bias[row]) : 0.0f;
            OT* cp = Cb + (size_t)row * NT + col0 + warpN + tig * 2;
#pragma unroll
            for (int nt = 0; nt < 4; nt++) {
                float v0 = acc[mt][nt][half * 2 + 0] + bv;
                float v1 = acc[mt][nt][half * 2 + 1] + bv;
                if (sizeof(OT) == 4) {
                    *(float2*)((float*)cp + nt * 8) = make_float2(v0, v1);
                } else {
                    __half2 hv = __floats2half2_rn(v0, v1);
                    *(__half2*)((__half*)cp + nt * 8) = hv;
                }
            }
        }
    }
}

// ---------------------------------------------------------------------------
// Tensor-core flash attention: one CTA per (b, h, g), 8 warps x 32 q-rows.
// Q,K in smem transposed [p][hd] fp16 (72-half rows); V in smem [hd][p]
// fp16 (264-half rows); mask words staged in smem. 32-key blocks, QK^T and
// PV on mma.sync.m16n8k16, online softmax on fragments with quad shfl
// reductions, P accumulator repacked as A fragments (FA2 layout identity).
// Output: transposed fp16 into g_aT for GEMM2.
// ---------------------------------------------------------------------------
#define QKP 72                       // halfs per Q/K smem row  (144 B)
#define VP  264                      // halfs per V smem row    (528 B)
#define SQ_OFF 0
#define SK_OFF (256 * QKP * 2)                 // 36864
#define SV_OFF (SK_OFF + 256 * QKP * 2)        // 73728
#define SM_OFF (SV_OFF + 64 * VP * 2)          // 107520
#define ATT_SMEM (SM_OFF + 8192)               // 115712

__global__ __launch_bounds__(256, 1) void attn_mma(const __half* __restrict__ qkv)
{
    const int g = blockIdx.x, h = blockIdx.y, b = blockIdx.z;
    const int tid = threadIdx.x, wid = tid >> 5, lane = tid & 31;

    extern __shared__ char smn[];
    __half* Qs = (__half*)(smn + SQ_OFF);
    __half* Ks = (__half*)(smn + SK_OFF);
    __half* Vs = (__half*)(smn + SV_OFF);
    unsigned* Ms = (unsigned*)(smn + SM_OFF);
    const uint32_t sb = smem_u32(smn);

    const __half* gq = qkv + ((size_t)b * E3D + h * HD) * GP + (size_t)g * PP;
    const __half* gk = gq + (size_t)DD * GP;
    const __half* gv = gq + (size_t)(2 * DD) * GP;

    // Q,K: transposed scatter [hd][p] -> [p][hd]
    for (int idx = tid; idx < 64 * 128; idx += 256) {
        int hd = idx >> 7;
        int p2 = (idx & 127) * 2;
        __half2 qv = *(const __half2*)(gq + (size_t)hd * GP + p2);
        __half2 kv = *(const __half2*)(gk + (size_t)hd * GP + p2);
        Qs[p2 * QKP + hd] = __low2half(qv);
        Qs[(p2 + 1) * QKP + hd] = __high2half(qv);
        Ks[p2 * QKP + hd] = __low2half(kv);
        Ks[(p2 + 1) * QKP + hd] = __high2half(kv);
    }
    // V: direct copy rows with pad
    for (int idx = tid; idx < 64 * 32; idx += 256) {
        int hd = idx >> 5, c = idx & 31;
        *(uint4*)(Vs + hd * VP + c * 8) = *(const uint4*)(gv + (size_t)hd * GP + c * 8);
    }
    // mask words for this group
    {
        const unsigned* mg = g_mask + (size_t)g * PP * 8;
        for (int idx = tid; idx < 2048; idx += 256) Ms[idx] = mg[idx];
    }
    __syncthreads();

    const int t0 = lane & 7, sel = lane >> 3;
    const int gID = lane >> 2, tig = lane & 3;
    const int rowbase = wid * 32;
    const float CC = 0.18033688011112042f;  // (1/8) * log2(e)

    // Q A-fragments: m32 x k64 (2 m-frags x 4 k-frags), resident all kernel
    uint32_t qa[2][4][4];
#pragma unroll
    for (int mt = 0; mt < 2; mt++)
#pragma unroll
        for (int kf = 0; kf < 4; kf++) {
            uint32_t ad = sb + SQ_OFF +
                (uint32_t)(rowbase + mt * 16 + t0 + (sel & 1) * 8) * (QKP * 2) +
                kf * 32 + (sel >> 1) * 16;
            ldsm4(qa[mt][kf][0], qa[mt][kf][1], qa[mt][kf][2], qa[mt][kf][3], ad);
        }

    float o[2][8][4];
#pragma unroll
    for (int mt = 0; mt < 2; mt++)
#pragma unroll
        for (int nh = 0; nh < 8; nh++)
#pragma unroll
            for (int r = 0; r < 4; r++) o[mt][nh][r] = 0.0f;
    float mrow[2][2] = {{-INFINITY, -INFINITY}, {-INFINITY, -INFINITY}};
    float lrow[2][2] = {{0.0f, 0.0f}, {0.0f, 0.0f}};

    for (int kb = 0; kb < 8; kb++) {         // 8 blocks of 32 keys
        // K B-fragments (keys = n, hd = k): B-style lane mapping
        uint32_t kbf[2][4][4];
#pragma unroll
        for (int np = 0; np < 2; np++)
#pragma unroll
            for (int kf = 0; kf < 4; kf++) {
                uint32_t ad = sb + SK_OFF +
                    (uint32_t)(kb * 32 + np * 16 + t0 + (sel >> 1) * 8) * (QKP * 2) +
                    kf * 32 + (sel & 1) * 16;
                ldsm4(kbf[np][kf][0], kbf[np][kf][1], kbf[np][kf][2], kbf[np][kf][3], ad);
            }

        // S = Q K^T  (m32 x n32, k64)
        float S[2][4][4];
#pragma unroll
        for (int mt = 0; mt < 2; mt++)
#pragma unroll
            for (int n4 = 0; n4 < 4; n4++) {
#pragma unroll
                for (int r = 0; r < 4; r++) S[mt][n4][r] = 0.0f;
#pragma unroll
                for (int kf = 0; kf < 4; kf++)
                    mma16816(S[mt][n4], qa[mt][kf], &kbf[n4 >> 1][kf][(n4 & 1) * 2]);
            }

        // scale + mask + online softmax (per m-frag, rows gID and gID+8)
#pragma unroll
        for (int mt = 0; mt < 2; mt++) {
            const unsigned w0 = Ms[(rowbase + mt * 16 + gID) * 8 + kb];
            const unsigned w1 = Ms[(rowbase + mt * 16 + gID + 8) * 8 + kb];
            float mx0 = -INFINITY, mx1 = -INFINITY;
#pragma unroll
            for (int n4 = 0; n4 < 4; n4++) {
                const int bb0 = n4 * 8 + tig * 2;
                float s0 = ((w0 >> bb0) & 1u) ? S[mt][n4][0] * CC : -1e30f;
                float s1 = ((w0 >> (bb0 + 1)) & 1u) ? S[mt][n4][1] * CC : -1e30f;
                float s2 = ((w1 >> bb0) & 1u) ? S[mt][n4][2] * CC : -1e30f;
                float s3 = ((w1 >> (bb0 + 1)) & 1u) ? S[mt][n4][3] * CC : -1e30f;
                S[mt][n4][0] = s0; S[mt][n4][1] = s1;
                S[mt][n4][2] = s2; S[mt][n4][3] = s3;
                mx0 = fmaxf(mx0, fmaxf(s0, s1));
                mx1 = fmaxf(mx1, fmaxf(s2, s3));
            }
            mx0 = fmaxf(mx0, __shfl_xor_sync(0xffffffffu, mx0, 1));
            mx0 = fmaxf(mx0, __shfl_xor_sync(0xffffffffu, mx0, 2));
            mx1 = fmaxf(mx1, __shfl_xor_sync(0xffffffffu, mx1, 1));
            mx1 = fmaxf(mx1, __shfl_xor_sync(0xffffffffu, mx1, 2));

            const float mn0 = fmaxf(mrow[mt][0], mx0);
            const float mn1 = fmaxf(mrow[mt][1], mx1);
            const float al0 = fexp2(mrow[mt][0] - mn0);
            const float al1 = fexp2(mrow[mt][1] - mn1);
            mrow[mt][0] = mn0; mrow[mt][1] = mn1;

            float sum0 = 0.0f, sum1 = 0.0f;
#pragma unroll
            for (int n4 = 0; n4 < 4; n4++) {
                float p0 = fexp2(S[mt][n4][0] - mn0);
                float p1 = fexp2(S[mt][n4][1] - mn0);
                float p2 = fexp2(S[mt][n4][2] - mn1);
                float p3 = fexp2(S[mt][n4][3] - mn1);
                S[mt][n4][0] = p0; S[mt][n4][1] = p1;
                S[mt][n4][2] = p2; S[mt][n4][3] = p3;
                sum0 += p0 + p1;
                sum1 += p2 + p3;
            }
            sum0 += __shfl_xor_sync(0xffffffffu, sum0, 1);
            sum0 += __shfl_xor_sync(0xffffffffu, sum0, 2);
            sum1 += __shfl_xor_sync(0xffffffffu, sum1, 1);
            sum1 += __shfl_xor_sync(0xffffffffu, sum1, 2);
            lrow[mt][0] = lrow[mt][0] * al0 + sum0;
            lrow[mt][1] = lrow[mt][1] * al1 + sum1;
#pragma unroll
            for (int nh = 0; nh < 8; nh++) {
                o[mt][nh][0] *= al0; o[mt][nh][1] *= al0;
                o[mt][nh][2] *= al1; o[mt][nh][3] *= al1;
            }
        }

        // P accumulator -> A fragments (half2 repack), k = 32 keys (2 kf)
        uint32_t pA[2][2][4];
#pragma unroll
        for (int mt = 0; mt < 2; mt++)
#pragma unroll
            for (int kf = 0; kf < 2; kf++) {
                pA[mt][kf][0] = h2pack(S[mt][2 * kf][0],     S[mt][2 * kf][1]);
                pA[mt][kf][1] = h2pack(S[mt][2 * kf][2],     S[mt][2 * kf][3]);
                pA[mt][kf][2] = h2pack(S[mt][2 * kf + 1][0], S[mt][2 * kf + 1][1]);
                pA[mt][kf][3] = h2pack(S[mt][2 * kf + 1][2], S[mt][2 * kf + 1][3]);
            }

        // O += P V  (V^T fragments from Vs[hd][p]: n = hd, k = keys)
#pragma unroll
        for (int nh2 = 0; nh2 < 4; nh2++)
#pragma unroll
            for (int kf = 0; kf < 2; kf++) {
                uint32_t vb[4];
                uint32_t ad = sb + SV_OFF +
                    (uint32_t)(nh2 * 16 + t0 + (sel >> 1) * 8) * (VP * 2) +
                    kb * 64 + kf * 32 + (sel & 1) * 16;
                ldsm4(vb[0], vb[1], vb[2], vb[3], ad);
#pragma unroll
                for (int mt = 0; mt < 2; mt++) {
                    mma16816(o[mt][nh2 * 2 + 0], pA[mt][kf], &vb[0]);
                    mma16816(o[mt][nh2 * 2 + 1], pA[mt][kf], &vb[2]);
                }
            }
    }

    // epilogue: normalize, fp16 round, transposed write into g_aT
#pragma unroll
    for (int mt = 0; mt < 2; mt++)
#pragma unroll
        for (int hh = 0; hh < 2; hh++) {
            const int r = rowbase + mt * 16 + gID + hh * 8;
            const float inv = 1.0f / lrow[mt][hh];
            __half* op = g_aT + ((size_t)b * GP + (size_t)g * PP + r) * DD + h * HD;
#pragma unroll
            for (int nh = 0; nh < 8; nh++) {
                __half2 hv = __floats2half2_rn(o[mt][nh][hh * 2 + 0] * inv,
                                               o[mt][nh][hh * 2 + 1] * inv);
                *(__half2*)(op + nh * 8 + tig * 2) = hv;
            }
        }
}

// ---------------------------------------------------------------------------
extern "C" void kernel_launch(void* const* d_in, const int* in_sizes, int n_in,
                              void* d_out, int out_size)
{
    const float* x      = (const float*)d_in[0];
    const void*  mask   = d_in[1];
    const float* w_qkv  = (const float*)d_in[2];
    const float* w_proj = (const float*)d_in[3];
    const float* b_proj = (const float*)d_in[4];
    float*       out    = (float*)d_out;

    __half *qkvbuf, *xt, *at, *wqh, *wql, *wph, *wpl;
    cudaGetSymbolAddress((void**)&qkvbuf, g_qkv);
    cudaGetSymbolAddress((void**)&xt, g_xT);
    cudaGetSymbolAddress((void**)&at, g_aT);
    cudaGetSymbolAddress((void**)&wqh, g_wq_hi);
    cudaGetSymbolAddress((void**)&wql, g_wq_lo);
    cudaGetSymbolAddress((void**)&wph, g_wp_hi);
    cudaGetSymbolAddress((void**)&wpl, g_wp_lo);

    // 0) mask dtype detection + bit packing
    detect_mask_dtype<<<1, 32>>>((const unsigned*)mask);
    pack_mask<<<(GG * PP * 8 + 255) / 256, 256>>>(mask);

    // 1) fp16 conversions
    conv_split<<<1024, 256>>>(w_qkv, wqh, wql, E3D * DD);
    conv_split<<<1024, 256>>>(w_proj, wph, wpl, DD * DD);
    conv_xT<<<dim3(GP / 32, DD / 32, BB), dim3(32, 8)>>>(x);

    const int GEMM1_SMEM = 2 * 20480;        // 40KB
    const int GEMM2_SMEM = 2 * 30720;        // 60KB
    cudaFuncSetAttribute((const void*)gemm_mma<1, __half>,
                         cudaFuncAttributeMaxDynamicSharedMemorySize, GEMM1_SMEM);
    cudaFuncSetAttribute((const void*)gemm_mma<2, float>,
                         cudaFuncAttributeMaxDynamicSharedMemorySize, GEMM2_SMEM);
    cudaFuncSetAttribute((const void*)attn_mma,
                         cudaFuncAttributeMaxDynamicSharedMemorySize, ATT_SMEM);

    // 2) QKV projection, 1-product fp16, fp16 output
    gemm_mma<1, __half><<<dim3(NT / 128, E3D / 128, BB), 256, GEMM1_SMEM>>>(
        wqh, nullptr, xt, qkvbuf, nullptr, E3D);

    // 3) tensor-core flash attention per (b, h, g)
    attn_mma<<<dim3(GG, HH, BB), 256, ATT_SMEM>>>(qkvbuf);

    // 4) output projection + bias, 2-product (weights exact)
    gemm_mma<2, float><<<dim3(NT / 128, DD / 128, BB), 256, GEMM2_SMEM>>>(
        wph, wpl, at, out, b_proj, DD);
}

// round 13
// speedup vs baseline: 2.6731x; 1.2552x over previous
#include <cuda_runtime.h>
#include <cuda_fp16.h>
#include <math.h>
#include <stdint.h>

// Problem constants
#define BB 4
#define DD 768
#define GG 64
#define PP 256
#define HH 12
#define HD 64
#define GP (GG * PP)            // 16384
#define E3D (3 * DD)            // 2304
#define KK 768                  // K dim of both GEMMs
#define NT GP                   // N total of both GEMMs

// ---------------- scratch (allocation-free rule: __device__ globals) -------
__device__ __align__(256) __half g_qkv[(size_t)BB * E3D * GP];  // fp16 qkv
__device__ __align__(256) __half g_xT[(size_t)BB * GP * DD];    // x^T [B,N,K]
__device__ __align__(256) __half g_aT[(size_t)BB * GP * DD];    // att^T fp16
__device__ __align__(256) __half g_wq_hi[(size_t)E3D * DD];
__device__ __align__(256) __half g_wq_lo[(size_t)E3D * DD];
__device__ __align__(256) __half g_wp_hi[(size_t)DD * DD];
__device__ __align__(256) __half g_wp_lo[(size_t)DD * DD];
__device__ unsigned g_mask[(size_t)GG * PP * 8];   // packed keep-bits per (g,p)
__device__ int g_mask_dtype;                       // 0=u8,1=i32,2=f32,3=bf16

typedef unsigned long long ull;

// ---------------- small PTX helpers ----------------------------------------
__device__ __forceinline__ uint32_t smem_u32(const void* p) {
    uint32_t a;
    asm("{ .reg .u64 t; cvta.to.shared.u64 t, %1; cvt.u32.u64 %0, t; }"
        : "=r"(a) : "l"(p));
    return a;
}
__device__ __forceinline__ void ldsm4(uint32_t& r0, uint32_t& r1, uint32_t& r2,
                                      uint32_t& r3, uint32_t addr) {
    asm volatile("ldmatrix.sync.aligned.m8n8.x4.shared.b16 {%0,%1,%2,%3}, [%4];"
                 : "=r"(r0), "=r"(r1), "=r"(r2), "=r"(r3) : "r"(addr));
}
__device__ __forceinline__ void mma16816(float* c, const uint32_t* a, const uint32_t* b) {
    asm volatile(
        "mma.sync.aligned.m16n8k16.row.col.f32.f16.f16.f32 "
        "{%0,%1,%2,%3}, {%4,%5,%6,%7}, {%8,%9}, {%0,%1,%2,%3};"
        : "+f"(c[0]), "+f"(c[1]), "+f"(c[2]), "+f"(c[3])
        : "r"(a[0]), "r"(a[1]), "r"(a[2]), "r"(a[3]), "r"(b[0]), "r"(b[1]));
}
__device__ __forceinline__ uint32_t h2pack(float a, float b) {
    __half2 h = __floats2half2_rn(a, b);
    return *(uint32_t*)&h;
}
__device__ __forceinline__ void cpa16(uint32_t dst, const void* src) {
    asm volatile("cp.async.cg.shared.global [%0], [%1], 16;" :: "r"(dst), "l"(src));
}
#define CPA_COMMIT() asm volatile("cp.async.commit_group;" ::: "memory")
#define CPA_WAIT1()  asm volatile("cp.async.wait_group 1;" ::: "memory")
#define CPA_WAIT0()  asm volatile("cp.async.wait_group 0;" ::: "memory")

// Fast exp2 entirely on FMA/ALU pipes (magic-constant round, no cvt pipe).
__device__ __forceinline__ float fexp2(float t) {
    t = fmaxf(t, -120.0f);
    float r = t + 12582912.0f;             // round-to-nearest-int in mantissa
    float f = t - (r - 12582912.0f);       // [-0.5, 0.5]
    int   sc = (__float_as_int(r) - 0x4B3FFF81) << 23;  // (n+127)<<23
    float p = 1.5403530e-4f;
    p = fmaf(p, f, 1.3333558e-3f);
    p = fmaf(p, f, 9.6181291e-3f);
    p = fmaf(p, f, 5.5504109e-2f);
    p = fmaf(p, f, 2.4022651e-1f);
    p = fmaf(p, f, 6.9314718e-1f);
    p = fmaf(p, f, 1.0f);
    return p * __int_as_float(sc);
}

// ---------------------------------------------------------------------------
// Mask dtype detection + packing
// ---------------------------------------------------------------------------
__global__ void detect_mask_dtype(const unsigned* __restrict__ m) {
    if (threadIdx.x != 0 || blockIdx.x != 0) return;
    int dt = 1;
    for (int i = 0; i < 1024; i++) {
        unsigned w = m[i];
        if (w == 0x3F800000u) { dt = 2; break; }
        if ((w & 0xFFFFu) == 0x3F80u || (w >> 16) == 0x3F80u) { dt = 3; break; }
        if (w > 1u) { dt = 0; break; }
    }
    g_mask_dtype = dt;
}

__global__ void pack_mask(const void* __restrict__ mraw) {
    int idx = blockIdx.x * blockDim.x + threadIdx.x;
    if (idx >= GG * PP * 8) return;
    int row = idx >> 3, w = idx & 7;
    int dt = g_mask_dtype;
    size_t base = (size_t)row * PP + w * 32;
    unsigned bits = 0;
    for (int t = 0; t < 32; t++) {
        bool keep;
        if (dt == 0)      keep = ((const unsigned char*)mraw)[base + t] != 0;
        else if (dt == 1) keep = ((const int*)mraw)[base + t] != 0;
        else if (dt == 2) keep = ((const float*)mraw)[base + t] != 0.0f;
        else              keep = ((const unsigned short*)mraw)[base + t] != 0;
        if (keep) bits |= 1u << t;
    }
    g_mask[idx] = bits;
}

// ---------------------------------------------------------------------------
// fp32 -> fp16 hi/lo split (weights, elementwise)
// ---------------------------------------------------------------------------
__global__ void conv_split(const float* __restrict__ in, __half* __restrict__ hi,
                           __half* __restrict__ lo, int n) {
    for (int i = blockIdx.x * blockDim.x + threadIdx.x; i < n; i += gridDim.x * blockDim.x) {
        float v = in[i];
        __half h = __float2half_rn(v);
        hi[i] = h;
        lo[i] = __float2half_rn(v - __half2float(h));
    }
}

// x [B, K=768, N=16384] fp32 -> xT [B, N, K] fp16 single (transposed round)
__global__ void conv_xT(const float* __restrict__ x) {
    __shared__ float t[32][33];
    int bz = blockIdx.z;
    int n0 = blockIdx.x * 32, k0 = blockIdx.y * 32;
    int tx = threadIdx.x, ty = threadIdx.y;
    const float* xp = x + ((size_t)bz * DD + k0) * GP + n0;
    for (int i = ty; i < 32; i += 8) t[i][tx] = xp[(size_t)i * GP + tx];
    __syncthreads();
    for (int r = ty; r < 32; r += 8) {
        size_t o = ((size_t)bz * GP + n0 + r) * DD + k0 + tx;
        g_xT[o] = __float2half_rn(t[tx][r]);
    }
}

// ---------------------------------------------------------------------------
// Warp-MMA GEMM, cp.async 3-stage pipeline, occupancy 2 CTAs/SM:
//   C[bz] = A @ B[bz]^T (+ bias), NPROD = 1 or 2, output type OT.
// CTA 128x128, 8 warps (2m x 4n), warp tile 64x32, K-chunk 32.
// cp.async frees prefetch registers so 2 CTAs/SM fit (<=128 regs/thread);
// two resident CTAs interleave load/barrier phases with MMA phases.
// ---------------------------------------------------------------------------
template <int NPROD, typename OT>
__global__ __launch_bounds__(256, 2) void gemm_mma(
    const __half* __restrict__ Ah, const __half* __restrict__ Al,
    const __half* __restrict__ B_,
    OT* __restrict__ C, const float* __restrict__ bias, int Mtot)
{
    extern __shared__ char smem[];
    constexpr uint32_t GOAH = 0u;
    constexpr uint32_t GOAL = 10240u;                        // only if NPROD==2
    constexpr uint32_t GOB  = (NPROD == 2) ? 20480u : 10240u;
    constexpr uint32_t GST  = GOB + 10240u;                  // stage stride

    const int tid = threadIdx.x;
    const int wid = tid >> 5, lane = tid & 31;
    const int bz = blockIdx.z;
    const int col0 = blockIdx.x * 128;   // N block (fastest)
    const int row0 = blockIdx.y * 128;   // M block
    const __half* B = B_ + (size_t)bz * NT * KK;
    OT* Cb = C + (size_t)bz * (size_t)Mtot * NT;

    const int warpM = (wid & 1) * 64;
    const int warpN = (wid >> 1) * 32;
    const uint32_t sb = smem_u32(smem);

    // per-thread load mapping: row = tid>>1, two 16B chunks at (tid&1)*32B
    const int lr = tid >> 1;
    const int lc = (tid & 1) * 2;
    const __half* pAh = Ah + (size_t)(row0 + lr) * KK + lc * 8;
    const __half* pAl = (NPROD == 2) ? (Al + (size_t)(row0 + lr) * KK + lc * 8) : nullptr;
    const __half* pB  = B  + (size_t)(col0 + lr) * KK + lc * 8;
    const uint32_t ss = lr * 80 + lc * 16;

    // ldmatrix lane roles
    const int t0 = lane & 7, sel = lane >> 3;
    const uint32_t a_lrow = (warpM + t0 + ((sel & 1) << 3)) * 80 + ((sel >> 1) << 4);
    const uint32_t b_lrow = (warpN + t0 + ((sel >> 1) << 3)) * 80 + ((sel & 1) << 4);

    float acc[4][4][4];
#pragma unroll
    for (int i = 0; i < 4; i++)
#pragma unroll
        for (int j = 0; j < 4; j++)
#pragma unroll
            for (int r = 0; r < 4; r++) acc[i][j][r] = 0.0f;

    const int NCH = KK / 32;   // 24

    auto issue = [&](int c) {
        const uint32_t so = sb + (uint32_t)(c % 3) * GST + ss;
        const size_t ko = (size_t)c * 32;
        cpa16(so + GOAH,      pAh + ko);  cpa16(so + GOAH + 16, pAh + ko + 8);
        if (NPROD == 2) {
            cpa16(so + GOAL,      pAl + ko);  cpa16(so + GOAL + 16, pAl + ko + 8);
        }
        cpa16(so + GOB,       pB  + ko);  cpa16(so + GOB  + 16, pB  + ko + 8);
    };

    issue(0); CPA_COMMIT();
    issue(1); CPA_COMMIT();

    for (int c = 0; c < NCH; c++) {
        if (c == NCH - 1) { CPA_WAIT0(); } else { CPA_WAIT1(); }
        __syncthreads();
        if (c + 2 < NCH) { issue(c + 2); CPA_COMMIT(); }

        const uint32_t so = sb + (uint32_t)(c % 3) * GST;
#pragma unroll
        for (int ks = 0; ks < 2; ks++) {
            uint32_t ah[4][4], al[4][4], bh[4][2];
#pragma unroll
            for (int mt = 0; mt < 4; mt++) {
                const uint32_t ad = so + a_lrow + mt * 16 * 80 + ks * 32;
                ldsm4(ah[mt][0], ah[mt][1], ah[mt][2], ah[mt][3], ad + GOAH);
                if (NPROD == 2)
                    ldsm4(al[mt][0], al[mt][1], al[mt][2], al[mt][3], ad + GOAL);
            }
#pragma unroll
            for (int ntp = 0; ntp < 2; ntp++) {
                const uint32_t bd = so + b_lrow + ntp * 16 * 80 + ks * 32;
                ldsm4(bh[2 * ntp][0], bh[2 * ntp][1], bh[2 * ntp + 1][0],
                      bh[2 * ntp + 1][1], bd + GOB);
            }
#pragma unroll
            for (int mt = 0; mt < 4; mt++)
#pragma unroll
                for (int nt = 0; nt < 4; nt++) {
                    mma16816(acc[mt][nt], ah[mt], bh[nt]);
                    if (NPROD == 2) mma16816(acc[mt][nt], al[mt], bh[nt]);
                }
        }
    }

    // epilogue: fragment -> gmem (float2 or half2), bias by M-row
    const int gID = lane >> 2, tig = lane & 3;
#pragma unroll
    for (int mt = 0; mt < 4; mt++) {
#pragma unroll
        for (int half = 0; half < 2; half++) {
            const int row = row0 + warpM + mt * 16 + gID + half * 8;
            const float bv = bias ? __ldg(&bias[row]) : 0.0f;
            OT* cp = Cb + (size_t)row * NT + col0 + warpN + tig * 2;
#pragma unroll
            for (int nt = 0; nt < 4; nt++) {
                float v0 = acc[mt][nt][half * 2 + 0] + bv;
                float v1 = acc[mt][nt][half * 2 + 1] + bv;
                if (sizeof(OT) == 4) {
                    *(float2*)((float*)cp + nt * 8) = make_float2(v0, v1);
                } else {
                    __half2 hv = __floats2half2_rn(v0, v1);
                    *(__half2*)((__half*)cp + nt * 8) = hv;
                }
            }
        }
    }
}

// ---------------------------------------------------------------------------
// Tensor-core flash attention (R11, unchanged): one CTA per (b, h, g),
// 8 warps x 32 q-rows, FA2 fragment softmax, fp16 transposed output.
// ---------------------------------------------------------------------------
#define QKP 72                       // halfs per Q/K smem row  (144 B)
#define VP  264                      // halfs per V smem row    (528 B)
#define SQ_OFF 0
#define SK_OFF (256 * QKP * 2)                 // 36864
#define SV_OFF (SK_OFF + 256 * QKP * 2)        // 73728
#define SM_OFF (SV_OFF + 64 * VP * 2)          // 107520
#define ATT_SMEM (SM_OFF + 8192)               // 115712

__global__ __launch_bounds__(256, 1) void attn_mma(const __half* __restrict__ qkv)
{
    const int g = blockIdx.x, h = blockIdx.y, b = blockIdx.z;
    const int tid = threadIdx.x, wid = tid >> 5, lane = tid & 31;

    extern __shared__ char smn[];
    __half* Qs = (__half*)(smn + SQ_OFF);
    __half* Ks = (__half*)(smn + SK_OFF);
    __half* Vs = (__half*)(smn + SV_OFF);
    unsigned* Ms = (unsigned*)(smn + SM_OFF);
    const uint32_t sb = smem_u32(smn);

    const __half* gq = qkv + ((size_t)b * E3D + h * HD) * GP + (size_t)g * PP;
    const __half* gk = gq + (size_t)DD * GP;
    const __half* gv = gq + (size_t)(2 * DD) * GP;

    // Q,K: transposed scatter [hd][p] -> [p][hd]
    for (int idx = tid; idx < 64 * 128; idx += 256) {
        int hd = idx >> 7;
        int p2 = (idx & 127) * 2;
        __half2 qv = *(const __half2*)(gq + (size_t)hd * GP + p2);
        __half2 kv = *(const __half2*)(gk + (size_t)hd * GP + p2);
        Qs[p2 * QKP + hd] = __low2half(qv);
        Qs[(p2 + 1) * QKP + hd] = __high2half(qv);
        Ks[p2 * QKP + hd] = __low2half(kv);
        Ks[(p2 + 1) * QKP + hd] = __high2half(kv);
    }
    // V: direct copy rows with pad
    for (int idx = tid; idx < 64 * 32; idx += 256) {
        int hd = idx >> 5, c = idx & 31;
        *(uint4*)(Vs + hd * VP + c * 8) = *(const uint4*)(gv + (size_t)hd * GP + c * 8);
    }
    // mask words for this group
    {
        const unsigned* mg = g_mask + (size_t)g * PP * 8;
        for (int idx = tid; idx < 2048; idx += 256) Ms[idx] = mg[idx];
    }
    __syncthreads();

    const int t0 = lane & 7, sel = lane >> 3;
    const int gID = lane >> 2, tig = lane & 3;
    const int rowbase = wid * 32;
    const float CC = 0.18033688011112042f;  // (1/8) * log2(e)

    // Q A-fragments: m32 x k64 (2 m-frags x 4 k-frags), resident all kernel
    uint32_t qa[2][4][4];
#pragma unroll
    for (int mt = 0; mt < 2; mt++)
#pragma unroll
        for (int kf = 0; kf < 4; kf++) {
            uint32_t ad = sb + SQ_OFF +
                (uint32_t)(rowbase + mt * 16 + t0 + (sel & 1) * 8) * (QKP * 2) +
                kf * 32 + (sel >> 1) * 16;
            ldsm4(qa[mt][kf][0], qa[mt][kf][1], qa[mt][kf][2], qa[mt][kf][3], ad);
        }

    float o[2][8][4];
#pragma unroll
    for (int mt = 0; mt < 2; mt++)
#pragma unroll
        for (int nh = 0; nh < 8; nh++)
#pragma unroll
            for (int r = 0; r < 4; r++) o[mt][nh][r] = 0.0f;
    float mrow[2][2] = {{-INFINITY, -INFINITY}, {-INFINITY, -INFINITY}};
    float lrow[2][2] = {{0.0f, 0.0f}, {0.0f, 0.0f}};

    for (int kb = 0; kb < 8; kb++) {         // 8 blocks of 32 keys
        uint32_t kbf[2][4][4];
#pragma unroll
        for (int np = 0; np < 2; np++)
#pragma unroll
            for (int kf = 0; kf < 4; kf++) {
                uint32_t ad = sb + SK_OFF +
                    (uint32_t)(kb * 32 + np * 16 + t0 + (sel >> 1) * 8) * (QKP * 2) +
                    kf * 32 + (sel & 1) * 16;
                ldsm4(kbf[np][kf][0], kbf[np][kf][1], kbf[np][kf][2], kbf[np][kf][3], ad);
            }

        float S[2][4][4];
#pragma unroll
        for (int mt = 0; mt < 2; mt++)
#pragma unroll
            for (int n4 = 0; n4 < 4; n4++) {
#pragma unroll
                for (int r = 0; r < 4; r++) S[mt][n4][r] = 0.0f;
#pragma unroll
                for (int kf = 0; kf < 4; kf++)
                    mma16816(S[mt][n4], qa[mt][kf], &kbf[n4 >> 1][kf][(n4 & 1) * 2]);
            }

#pragma unroll
        for (int mt = 0; mt < 2; mt++) {
            const unsigned w0 = Ms[(rowbase + mt * 16 + gID) * 8 + kb];
            const unsigned w1 = Ms[(rowbase + mt * 16 + gID + 8) * 8 + kb];
            float mx0 = -INFINITY, mx1 = -INFINITY;
#pragma unroll
            for (int n4 = 0; n4 < 4; n4++) {
                const int bb0 = n4 * 8 + tig * 2;
                float s0 = ((w0 >> bb0) & 1u) ? S[mt][n4][0] * CC : -1e30f;
                float s1 = ((w0 >> (bb0 + 1)) & 1u) ? S[mt][n4][1] * CC : -1e30f;
                float s2 = ((w1 >> bb0) & 1u) ? S[mt][n4][2] * CC : -1e30f;
                float s3 = ((w1 >> (bb0 + 1)) & 1u) ? S[mt][n4][3] * CC : -1e30f;
                S[mt][n4][0] = s0; S[mt][n4][1] = s1;
                S[mt][n4][2] = s2; S[mt][n4][3] = s3;
                mx0 = fmaxf(mx0, fmaxf(s0, s1));
                mx1 = fmaxf(mx1, fmaxf(s2, s3));
            }
            mx0 = fmaxf(mx0, __shfl_xor_sync(0xffffffffu, mx0, 1));
            mx0 = fmaxf(mx0, __shfl_xor_sync(0xffffffffu, mx0, 2));
            mx1 = fmaxf(mx1, __shfl_xor_sync(0xffffffffu, mx1, 1));
            mx1 = fmaxf(mx1, __shfl_xor_sync(0xffffffffu, mx1, 2));

            const float mn0 = fmaxf(mrow[mt][0], mx0);
            const float mn1 = fmaxf(mrow[mt][1], mx1);
            const float al0 = fexp2(mrow[mt][0] - mn0);
            const float al1 = fexp2(mrow[mt][1] - mn1);
            mrow[mt][0] = mn0; mrow[mt][1] = mn1;

            float sum0 = 0.0f, sum1 = 0.0f;
#pragma unroll
            for (int n4 = 0; n4 < 4; n4++) {
                float p0 = fexp2(S[mt][n4][0] - mn0);
                float p1 = fexp2(S[mt][n4][1] - mn0);
                float p2 = fexp2(S[mt][n4][2] - mn1);
                float p3 = fexp2(S[mt][n4][3] - mn1);
                S[mt][n4][0] = p0; S[mt][n4][1] = p1;
                S[mt][n4][2] = p2; S[mt][n4][3] = p3;
                sum0 += p0 + p1;
                sum1 += p2 + p3;
            }
            sum0 += __shfl_xor_sync(0xffffffffu, sum0, 1);
            sum0 += __shfl_xor_sync(0xffffffffu, sum0, 2);
            sum1 += __shfl_xor_sync(0xffffffffu, sum1, 1);
            sum1 += __shfl_xor_sync(0xffffffffu, sum1, 2);
            lrow[mt][0] = lrow[mt][0] * al0 + sum0;
            lrow[mt][1] = lrow[mt][1] * al1 + sum1;
#pragma unroll
            for (int nh = 0; nh < 8; nh++) {
                o[mt][nh][0] *= al0; o[mt][nh][1] *= al0;
                o[mt][nh][2] *= al1; o[mt][nh][3] *= al1;
            }
        }

        uint32_t pA[2][2][4];
#pragma unroll
        for (int mt = 0; mt < 2; mt++)
#pragma unroll
            for (int kf = 0; kf < 2; kf++) {
                pA[mt][kf][0] = h2pack(S[mt][2 * kf][0],     S[mt][2 * kf][1]);
                pA[mt][kf][1] = h2pack(S[mt][2 * kf][2],     S[mt][2 * kf][3]);
                pA[mt][kf][2] = h2pack(S[mt][2 * kf + 1][0], S[mt][2 * kf + 1][1]);
                pA[mt][kf][3] = h2pack(S[mt][2 * kf + 1][2], S[mt][2 * kf + 1][3]);
            }

#pragma unroll
        for (int nh2 = 0; nh2 < 4; nh2++)
#pragma unroll
            for (int kf = 0; kf < 2; kf++) {
                uint32_t vb[4];
                uint32_t ad = sb + SV_OFF +
                    (uint32_t)(nh2 * 16 + t0 + (sel >> 1) * 8) * (VP * 2) +
                    kb * 64 + kf * 32 + (sel & 1) * 16;
                ldsm4(vb[0], vb[1], vb[2], vb[3], ad);
#pragma unroll
                for (int mt = 0; mt < 2; mt++) {
                    mma16816(o[mt][nh2 * 2 + 0], pA[mt][kf], &vb[0]);
                    mma16816(o[mt][nh2 * 2 + 1], pA[mt][kf], &vb[2]);
                }
            }
    }

#pragma unroll
    for (int mt = 0; mt < 2; mt++)
#pragma unroll
        for (int hh = 0; hh < 2; hh++) {
            const int r = rowbase + mt * 16 + gID + hh * 8;
            const float inv = 1.0f / lrow[mt][hh];
            __half* op = g_aT + ((size_t)b * GP + (size_t)g * PP + r) * DD + h * HD;
#pragma unroll
            for (int nh = 0; nh < 8; nh++) {
                __half2 hv = __floats2half2_rn(o[mt][nh][hh * 2 + 0] * inv,
                                               o[mt][nh][hh * 2 + 1] * inv);
                *(__half2*)(op + nh * 8 + tig * 2) = hv;
            }
        }
}

// ---------------------------------------------------------------------------
extern "C" void kernel_launch(void* const* d_in, const int* in_sizes, int n_in,
                              void* d_out, int out_size)
{
    const float* x      = (const float*)d_in[0];
    const void*  mask   = d_in[1];
    const float* w_qkv  = (const float*)d_in[2];
    const float* w_proj = (const float*)d_in[3];
    const float* b_proj = (const float*)d_in[4];
    float*       out    = (float*)d_out;

    __half *qkvbuf, *xt, *at, *wqh, *wql, *wph, *wpl;
    cudaGetSymbolAddress((void**)&qkvbuf, g_qkv);
    cudaGetSymbolAddress((void**)&xt, g_xT);
    cudaGetSymbolAddress((void**)&at, g_aT);
    cudaGetSymbolAddress((void**)&wqh, g_wq_hi);
    cudaGetSymbolAddress((void**)&wql, g_wq_lo);
    cudaGetSymbolAddress((void**)&wph, g_wp_hi);
    cudaGetSymbolAddress((void**)&wpl, g_wp_lo);

    // 0) mask dtype detection + bit packing
    detect_mask_dtype<<<1, 32>>>((const unsigned*)mask);
    pack_mask<<<(GG * PP * 8 + 255) / 256, 256>>>(mask);

    // 1) fp16 conversions
    conv_split<<<1024, 256>>>(w_qkv, wqh, wql, E3D * DD);
    conv_split<<<1024, 256>>>(w_proj, wph, wpl, DD * DD);
    conv_xT<<<dim3(GP / 32, DD / 32, BB), dim3(32, 8)>>>(x);

    const int GEMM1_SMEM = 3 * 20480;        // 60KB -> 2 CTAs/SM = 120KB
    const int GEMM2_SMEM = 3 * 30720;        // 90KB -> 2 CTAs/SM = 180KB
    cudaFuncSetAttribute((const void*)gemm_mma<1, __half>,
                         cudaFuncAttributeMaxDynamicSharedMemorySize, GEMM1_SMEM);
    cudaFuncSetAttribute((const void*)gemm_mma<2, float>,
                         cudaFuncAttributeMaxDynamicSharedMemorySize, GEMM2_SMEM);
    cudaFuncSetAttribute((const void*)attn_mma,
                         cudaFuncAttributeMaxDynamicSharedMemorySize, ATT_SMEM);

    // 2) QKV projection, 1-product fp16, fp16 output
    gemm_mma<1, __half><<<dim3(NT / 128, E3D / 128, BB), 256, GEMM1_SMEM>>>(
        wqh, nullptr, xt, qkvbuf, nullptr, E3D);

    // 3) tensor-core flash attention per (b, h, g)
    attn_mma<<<dim3(GG, HH, BB), 256, ATT_SMEM>>>(qkvbuf);

    // 4) output projection + bias, 2-product (weights exact)
    gemm_mma<2, float><<<dim3(NT / 128, DD / 128, BB), 256, GEMM2_SMEM>>>(
        wph, wpl, at, out, b_proj, DD);
}

// round 14
// speedup vs baseline: 2.9968x; 1.1211x over previous
#include <cuda_runtime.h>
#include <cuda_fp16.h>
#include <math.h>
#include <stdint.h>

// Problem constants
#define BB 4
#define DD 768
#define GG 64
#define PP 256
#define HH 12
#define HD 64
#define GP (GG * PP)            // 16384
#define E3D (3 * DD)            // 2304
#define KK 768                  // K dim of both GEMMs
#define NT GP                   // N total of both GEMMs

// ---------------- scratch (allocation-free rule: __device__ globals) -------
__device__ __align__(256) __half g_qkv[(size_t)BB * E3D * GP];  // fp16 qkv
__device__ __align__(256) __half g_xT[(size_t)BB * GP * DD];    // x^T [B,N,K]
__device__ __align__(256) __half g_aT[(size_t)BB * GP * DD];    // att^T fp16
__device__ __align__(256) __half g_wq[(size_t)E3D * DD];        // w_qkv fp16
__device__ __align__(256) __half g_wp[(size_t)DD * DD];         // w_proj fp16
__device__ unsigned g_mask[(size_t)GG * PP * 8];   // packed keep-bits per (g,p)
__device__ int g_mask_dtype;                       // 0=u8,1=i32,2=f32,3=bf16

typedef unsigned long long ull;

// ---------------- small PTX helpers ----------------------------------------
__device__ __forceinline__ uint32_t smem_u32(const void* p) {
    uint32_t a;
    asm("{ .reg .u64 t; cvta.to.shared.u64 t, %1; cvt.u32.u64 %0, t; }"
        : "=r"(a) : "l"(p));
    return a;
}
__device__ __forceinline__ void ldsm4(uint32_t& r0, uint32_t& r1, uint32_t& r2,
                                      uint32_t& r3, uint32_t addr) {
    asm volatile("ldmatrix.sync.aligned.m8n8.x4.shared.b16 {%0,%1,%2,%3}, [%4];"
                 : "=r"(r0), "=r"(r1), "=r"(r2), "=r"(r3) : "r"(addr));
}
__device__ __forceinline__ void mma16816(float* c, const uint32_t* a, const uint32_t* b) {
    asm volatile(
        "mma.sync.aligned.m16n8k16.row.col.f32.f16.f16.f32 "
        "{%0,%1,%2,%3}, {%4,%5,%6,%7}, {%8,%9}, {%0,%1,%2,%3};"
        : "+f"(c[0]), "+f"(c[1]), "+f"(c[2]), "+f"(c[3])
        : "r"(a[0]), "r"(a[1]), "r"(a[2]), "r"(a[3]), "r"(b[0]), "r"(b[1]));
}
__device__ __forceinline__ uint32_t h2pack(float a, float b) {
    __half2 h = __floats2half2_rn(a, b);
    return *(uint32_t*)&h;
}
__device__ __forceinline__ void cpa16(uint32_t dst, const void* src) {
    asm volatile("cp.async.cg.shared.global [%0], [%1], 16;" :: "r"(dst), "l"(src));
}
#define CPA_COMMIT() asm volatile("cp.async.commit_group;" ::: "memory")
#define CPA_WAIT1()  asm volatile("cp.async.wait_group 1;" ::: "memory")
#define CPA_WAIT0()  asm volatile("cp.async.wait_group 0;" ::: "memory")

// Fast exp2 entirely on FMA/ALU pipes (magic-constant round, no cvt pipe).
__device__ __forceinline__ float fexp2(float t) {
    t = fmaxf(t, -120.0f);
    float r = t + 12582912.0f;             // round-to-nearest-int in mantissa
    float f = t - (r - 12582912.0f);       // [-0.5, 0.5]
    int   sc = (__float_as_int(r) - 0x4B3FFF81) << 23;  // (n+127)<<23
    float p = 1.5403530e-4f;
    p = fmaf(p, f, 1.3333558e-3f);
    p = fmaf(p, f, 9.6181291e-3f);
    p = fmaf(p, f, 5.5504109e-2f);
    p = fmaf(p, f, 2.4022651e-1f);
    p = fmaf(p, f, 6.9314718e-1f);
    p = fmaf(p, f, 1.0f);
    return p * __int_as_float(sc);
}

// ---------------------------------------------------------------------------
// Mask dtype detection + packing
// ---------------------------------------------------------------------------
__global__ void detect_mask_dtype(const unsigned* __restrict__ m) {
    if (threadIdx.x != 0 || blockIdx.x != 0) return;
    int dt = 1;
    for (int i = 0; i < 1024; i++) {
        unsigned w = m[i];
        if (w == 0x3F800000u) { dt = 2; break; }
        if ((w & 0xFFFFu) == 0x3F80u || (w >> 16) == 0x3F80u) { dt = 3; break; }
        if (w > 1u) { dt = 0; break; }
    }
    g_mask_dtype = dt;
}

__global__ void pack_mask(const void* __restrict__ mraw) {
    int idx = blockIdx.x * blockDim.x + threadIdx.x;
    if (idx >= GG * PP * 8) return;
    int row = idx >> 3, w = idx & 7;
    int dt = g_mask_dtype;
    size_t base = (size_t)row * PP + w * 32;
    unsigned bits = 0;
    for (int t = 0; t < 32; t++) {
        bool keep;
        if (dt == 0)      keep = ((const unsigned char*)mraw)[base + t] != 0;
        else if (dt == 1) keep = ((const int*)mraw)[base + t] != 0;
        else if (dt == 2) keep = ((const float*)mraw)[base + t] != 0.0f;
        else              keep = ((const unsigned short*)mraw)[base + t] != 0;
        if (keep) bits |= 1u << t;
    }
    g_mask[idx] = bits;
}

// ---------------------------------------------------------------------------
// fp32 -> fp16 round (weights, elementwise)
// ---------------------------------------------------------------------------
__global__ void conv_round(const float* __restrict__ in, __half* __restrict__ hi, int n) {
    for (int i = blockIdx.x * blockDim.x + threadIdx.x; i < n; i += gridDim.x * blockDim.x)
        hi[i] = __float2half_rn(in[i]);
}

// x [B, K=768, N=16384] fp32 -> xT [B, N, K] fp16 single (transposed round)
__global__ void conv_xT(const float* __restrict__ x) {
    __shared__ float t[32][33];
    int bz = blockIdx.z;
    int n0 = blockIdx.x * 32, k0 = blockIdx.y * 32;
    int tx = threadIdx.x, ty = threadIdx.y;
    const float* xp = x + ((size_t)bz * DD + k0) * GP + n0;
    for (int i = ty; i < 32; i += 8) t[i][tx] = xp[(size_t)i * GP + tx];
    __syncthreads();
    for (int r = ty; r < 32; r += 8) {
        size_t o = ((size_t)bz * GP + n0 + r) * DD + k0 + tx;
        g_xT[o] = __float2half_rn(t[tx][r]);
    }
}

// ---------------------------------------------------------------------------
// Warp-MMA GEMM, cp.async 3-stage pipeline, occupancy 2 CTAs/SM:
//   C[bz] = A @ B[bz]^T (+ bias), pure fp16 1-product, output type OT.
// CTA 128x128, 8 warps (2m x 4n), warp tile 64x32, K-chunk 32.
// ---------------------------------------------------------------------------
#define GOA 0u
#define GOB 10240u
#define GST 20480u

template <typename OT>
__global__ __launch_bounds__(256, 2) void gemm_mma(
    const __half* __restrict__ A_, const __half* __restrict__ B_,
    OT* __restrict__ C, const float* __restrict__ bias, int Mtot)
{
    extern __shared__ char smem[];
    const int tid = threadIdx.x;
    const int wid = tid >> 5, lane = tid & 31;
    const int bz = blockIdx.z;
    const int col0 = blockIdx.x * 128;   // N block (fastest)
    const int row0 = blockIdx.y * 128;   // M block
    const __half* B = B_ + (size_t)bz * NT * KK;
    OT* Cb = C + (size_t)bz * (size_t)Mtot * NT;

    const int warpM = (wid & 1) * 64;
    const int warpN = (wid >> 1) * 32;
    const uint32_t sb = smem_u32(smem);

    // per-thread load mapping: row = tid>>1, two 16B chunks at (tid&1)*32B
    const int lr = tid >> 1;
    const int lc = (tid & 1) * 2;
    const __half* pA = A_ + (size_t)(row0 + lr) * KK + lc * 8;
    const __half* pB = B  + (size_t)(col0 + lr) * KK + lc * 8;
    const uint32_t ss = lr * 80 + lc * 16;

    // ldmatrix lane roles
    const int t0 = lane & 7, sel = lane >> 3;
    const uint32_t a_lrow = (warpM + t0 + ((sel & 1) << 3)) * 80 + ((sel >> 1) << 4);
    const uint32_t b_lrow = (warpN + t0 + ((sel >> 1) << 3)) * 80 + ((sel & 1) << 4);

    float acc[4][4][4];
#pragma unroll
    for (int i = 0; i < 4; i++)
#pragma unroll
        for (int j = 0; j < 4; j++)
#pragma unroll
            for (int r = 0; r < 4; r++) acc[i][j][r] = 0.0f;

    const int NCH = KK / 32;   // 24

    auto issue = [&](int c) {
        const uint32_t so = sb + (uint32_t)(c % 3) * GST + ss;
        const size_t ko = (size_t)c * 32;
        cpa16(so + GOA,      pA + ko);  cpa16(so + GOA + 16, pA + ko + 8);
        cpa16(so + GOB,      pB + ko);  cpa16(so + GOB + 16, pB + ko + 8);
    };

    issue(0); CPA_COMMIT();
    issue(1); CPA_COMMIT();

    for (int c = 0; c < NCH; c++) {
        if (c == NCH - 1) { CPA_WAIT0(); } else { CPA_WAIT1(); }
        __syncthreads();
        if (c + 2 < NCH) { issue(c + 2); CPA_COMMIT(); }

        const uint32_t so = sb + (uint32_t)(c % 3) * GST;
#pragma unroll
        for (int ks = 0; ks < 2; ks++) {
            uint32_t ah[4][4], bh[4][2];
#pragma unroll
            for (int mt = 0; mt < 4; mt++) {
                const uint32_t ad = so + a_lrow + mt * 16 * 80 + ks * 32;
                ldsm4(ah[mt][0], ah[mt][1], ah[mt][2], ah[mt][3], ad + GOA);
            }
#pragma unroll
            for (int ntp = 0; ntp < 2; ntp++) {
                const uint32_t bd = so + b_lrow + ntp * 16 * 80 + ks * 32;
                ldsm4(bh[2 * ntp][0], bh[2 * ntp][1], bh[2 * ntp + 1][0],
                      bh[2 * ntp + 1][1], bd + GOB);
            }
#pragma unroll
            for (int mt = 0; mt < 4; mt++)
#pragma unroll
                for (int nt = 0; nt < 4; nt++)
                    mma16816(acc[mt][nt], ah[mt], bh[nt]);
        }
    }

    // epilogue: fragment -> gmem (float2 or half2), bias by M-row
    const int gID = lane >> 2, tig = lane & 3;
#pragma unroll
    for (int mt = 0; mt < 4; mt++) {
#pragma unroll
        for (int half = 0; half < 2; half++) {
            const int row = row0 + warpM + mt * 16 + gID + half * 8;
            const float bv = bias ? __ldg(&bias[row]) : 0.0f;
            OT* cp = Cb + (size_t)row * NT + col0 + warpN + tig * 2;
#pragma unroll
            for (int nt = 0; nt < 4; nt++) {
                float v0 = acc[mt][nt][half * 2 + 0] + bv;
                float v1 = acc[mt][nt][half * 2 + 1] + bv;
                if (sizeof(OT) == 4) {
                    *(float2*)((float*)cp + nt * 8) = make_float2(v0, v1);
                } else {
                    __half2 hv = __floats2half2_rn(v0, v1);
                    *(__half2*)((__half*)cp + nt * 8) = hv;
                }
            }
        }
    }
}

// ---------------------------------------------------------------------------
// Tensor-core flash attention (R11, unchanged): one CTA per (b, h, g),
// 8 warps x 32 q-rows, FA2 fragment softmax, fp16 transposed output.
// ---------------------------------------------------------------------------
#define QKP 72                       // halfs per Q/K smem row  (144 B)
#define VP  264                      // halfs per V smem row    (528 B)
#define SQ_OFF 0
#define SK_OFF (256 * QKP * 2)                 // 36864
#define SV_OFF (SK_OFF + 256 * QKP * 2)        // 73728
#define SM_OFF (SV_OFF + 64 * VP * 2)          // 107520
#define ATT_SMEM (SM_OFF + 8192)               // 115712

__global__ __launch_bounds__(256, 1) void attn_mma(const __half* __restrict__ qkv)
{
    const int g = blockIdx.x, h = blockIdx.y, b = blockIdx.z;
    const int tid = threadIdx.x, wid = tid >> 5, lane = tid & 31;

    extern __shared__ char smn[];
    __half* Qs = (__half*)(smn + SQ_OFF);
    __half* Ks = (__half*)(smn + SK_OFF);
    __half* Vs = (__half*)(smn + SV_OFF);
    unsigned* Ms = (unsigned*)(smn + SM_OFF);
    const uint32_t sb = smem_u32(smn);

    const __half* gq = qkv + ((size_t)b * E3D + h * HD) * GP + (size_t)g * PP;
    const __half* gk = gq + (size_t)DD * GP;
    const __half* gv = gq + (size_t)(2 * DD) * GP;

    // Q,K: transposed scatter [hd][p] -> [p][hd]
    for (int idx = tid; idx < 64 * 128; idx += 256) {
        int hd = idx >> 7;
        int p2 = (idx & 127) * 2;
        __half2 qv = *(const __half2*)(gq + (size_t)hd * GP + p2);
        __half2 kv = *(const __half2*)(gk + (size_t)hd * GP + p2);
        Qs[p2 * QKP + hd] = __low2half(qv);
        Qs[(p2 + 1) * QKP + hd] = __high2half(qv);
        Ks[p2 * QKP + hd] = __low2half(kv);
        Ks[(p2 + 1) * QKP + hd] = __high2half(kv);
    }
    // V: direct copy rows with pad
    for (int idx = tid; idx < 64 * 32; idx += 256) {
        int hd = idx >> 5, c = idx & 31;
        *(uint4*)(Vs + hd * VP + c * 8) = *(const uint4*)(gv + (size_t)hd * GP + c * 8);
    }
    // mask words for this group
    {
        const unsigned* mg = g_mask + (size_t)g * PP * 8;
        for (int idx = tid; idx < 2048; idx += 256) Ms[idx] = mg[idx];
    }
    __syncthreads();

    const int t0 = lane & 7, sel = lane >> 3;
    const int gID = lane >> 2, tig = lane & 3;
    const int rowbase = wid * 32;
    const float CC = 0.18033688011112042f;  // (1/8) * log2(e)

    // Q A-fragments: m32 x k64 (2 m-frags x 4 k-frags), resident all kernel
    uint32_t qa[2][4][4];
#pragma unroll
    for (int mt = 0; mt < 2; mt++)
#pragma unroll
        for (int kf = 0; kf < 4; kf++) {
            uint32_t ad = sb + SQ_OFF +
                (uint32_t)(rowbase + mt * 16 + t0 + (sel & 1) * 8) * (QKP * 2) +
                kf * 32 + (sel >> 1) * 16;
            ldsm4(qa[mt][kf][0], qa[mt][kf][1], qa[mt][kf][2], qa[mt][kf][3], ad);
        }

    float o[2][8][4];
#pragma unroll
    for (int mt = 0; mt < 2; mt++)
#pragma unroll
        for (int nh = 0; nh < 8; nh++)
#pragma unroll
            for (int r = 0; r < 4; r++) o[mt][nh][r] = 0.0f;
    float mrow[2][2] = {{-INFINITY, -INFINITY}, {-INFINITY, -INFINITY}};
    float lrow[2][2] = {{0.0f, 0.0f}, {0.0f, 0.0f}};

    for (int kb = 0; kb < 8; kb++) {         // 8 blocks of 32 keys
        uint32_t kbf[2][4][4];
#pragma unroll
        for (int np = 0; np < 2; np++)
#pragma unroll
            for (int kf = 0; kf < 4; kf++) {
                uint32_t ad = sb + SK_OFF +
                    (uint32_t)(kb * 32 + np * 16 + t0 + (sel >> 1) * 8) * (QKP * 2) +
                    kf * 32 + (sel & 1) * 16;
                ldsm4(kbf[np][kf][0], kbf[np][kf][1], kbf[np][kf][2], kbf[np][kf][3], ad);
            }

        float S[2][4][4];
#pragma unroll
        for (int mt = 0; mt < 2; mt++)
#pragma unroll
            for (int n4 = 0; n4 < 4; n4++) {
#pragma unroll
                for (int r = 0; r < 4; r++) S[mt][n4][r] = 0.0f;
#pragma unroll
                for (int kf = 0; kf < 4; kf++)
                    mma16816(S[mt][n4], qa[mt][kf], &kbf[n4 >> 1][kf][(n4 & 1) * 2]);
            }

#pragma unroll
        for (int mt = 0; mt < 2; mt++) {
            const unsigned w0 = Ms[(rowbase + mt * 16 + gID) * 8 + kb];
            const unsigned w1 = Ms[(rowbase + mt * 16 + gID + 8) * 8 + kb];
            float mx0 = -INFINITY, mx1 = -INFINITY;
#pragma unroll
            for (int n4 = 0; n4 < 4; n4++) {
                const int bb0 = n4 * 8 + tig * 2;
                float s0 = ((w0 >> bb0) & 1u) ? S[mt][n4][0] * CC : -1e30f;
                float s1 = ((w0 >> (bb0 + 1)) & 1u) ? S[mt][n4][1] * CC : -1e30f;
                float s2 = ((w1 >> bb0) & 1u) ? S[mt][n4][2] * CC : -1e30f;
                float s3 = ((w1 >> (bb0 + 1)) & 1u) ? S[mt][n4][3] * CC : -1e30f;
                S[mt][n4][0] = s0; S[mt][n4][1] = s1;
                S[mt][n4][2] = s2; S[mt][n4][3] = s3;
                mx0 = fmaxf(mx0, fmaxf(s0, s1));
                mx1 = fmaxf(mx1, fmaxf(s2, s3));
            }
            mx0 = fmaxf(mx0, __shfl_xor_sync(0xffffffffu, mx0, 1));
            mx0 = fmaxf(mx0, __shfl_xor_sync(0xffffffffu, mx0, 2));
            mx1 = fmaxf(mx1, __shfl_xor_sync(0xffffffffu, mx1, 1));
            mx1 = fmaxf(mx1, __shfl_xor_sync(0xffffffffu, mx1, 2));

            const float mn0 = fmaxf(mrow[mt][0], mx0);
            const float mn1 = fmaxf(mrow[mt][1], mx1);
            const float al0 = fexp2(mrow[mt][0] - mn0);
            const float al1 = fexp2(mrow[mt][1] - mn1);
            mrow[mt][0] = mn0; mrow[mt][1] = mn1;

            float sum0 = 0.0f, sum1 = 0.0f;
#pragma unroll
            for (int n4 = 0; n4 < 4; n4++) {
                float p0 = fexp2(S[mt][n4][0] - mn0);
                float p1 = fexp2(S[mt][n4][1] - mn0);
                float p2 = fexp2(S[mt][n4][2] - mn1);
                float p3 = fexp2(S[mt][n4][3] - mn1);
                S[mt][n4][0] = p0; S[mt][n4][1] = p1;
                S[mt][n4][2] = p2; S[mt][n4][3] = p3;
                sum0 += p0 + p1;
                sum1 += p2 + p3;
            }
            sum0 += __shfl_xor_sync(0xffffffffu, sum0, 1);
            sum0 += __shfl_xor_sync(0xffffffffu, sum0, 2);
            sum1 += __shfl_xor_sync(0xffffffffu, sum1, 1);
            sum1 += __shfl_xor_sync(0xffffffffu, sum1, 2);
            lrow[mt][0] = lrow[mt][0] * al0 + sum0;
            lrow[mt][1] = lrow[mt][1] * al1 + sum1;
#pragma unroll
            for (int nh = 0; nh < 8; nh++) {
                o[mt][nh][0] *= al0; o[mt][nh][1] *= al0;
                o[mt][nh][2] *= al1; o[mt][nh][3] *= al1;
            }
        }

        uint32_t pA[2][2][4];
#pragma unroll
        for (int mt = 0; mt < 2; mt++)
#pragma unroll
            for (int kf = 0; kf < 2; kf++) {
                pA[mt][kf][0] = h2pack(S[mt][2 * kf][0],     S[mt][2 * kf][1]);
                pA[mt][kf][1] = h2pack(S[mt][2 * kf][2],     S[mt][2 * kf][3]);
                pA[mt][kf][2] = h2pack(S[mt][2 * kf + 1][0], S[mt][2 * kf + 1][1]);
                pA[mt][kf][3] = h2pack(S[mt][2 * kf + 1][2], S[mt][2 * kf + 1][3]);
            }

#pragma unroll
        for (int nh2 = 0; nh2 < 4; nh2++)
#pragma unroll
            for (int kf = 0; kf < 2; kf++) {
                uint32_t vb[4];
                uint32_t ad = sb + SV_OFF +
                    (uint32_t)(nh2 * 16 + t0 + (sel >> 1) * 8) * (VP * 2) +
                    kb * 64 + kf * 32 + (sel & 1) * 16;
                ldsm4(vb[0], vb[1], vb[2], vb[3], ad);
#pragma unroll
                for (int mt = 0; mt < 2; mt++) {
                    mma16816(o[mt][nh2 * 2 + 0], pA[mt][kf], &vb[0]);
                    mma16816(o[mt][nh2 * 2 + 1], pA[mt][kf], &vb[2]);
                }
            }
    }

#pragma unroll
    for (int mt = 0; mt < 2; mt++)
#pragma unroll
        for (int hh = 0; hh < 2; hh++) {
            const int r = rowbase + mt * 16 + gID + hh * 8;
            const float inv = 1.0f / lrow[mt][hh];
            __half* op = g_aT + ((size_t)b * GP + (size_t)g * PP + r) * DD + h * HD;
#pragma unroll
            for (int nh = 0; nh < 8; nh++) {
                __half2 hv = __floats2half2_rn(o[mt][nh][hh * 2 + 0] * inv,
                                               o[mt][nh][hh * 2 + 1] * inv);
                *(__half2*)(op + nh * 8 + tig * 2) = hv;
            }
        }
}

// ---------------------------------------------------------------------------
extern "C" void kernel_launch(void* const* d_in, const int* in_sizes, int n_in,
                              void* d_out, int out_size)
{
    const float* x      = (const float*)d_in[0];
    const void*  mask   = d_in[1];
    const float* w_qkv  = (const float*)d_in[2];
    const float* w_proj = (const float*)d_in[3];
    const float* b_proj = (const float*)d_in[4];
    float*       out    = (float*)d_out;

    __half *qkvbuf, *xt, *at, *wq, *wp;
    cudaGetSymbolAddress((void**)&qkvbuf, g_qkv);
    cudaGetSymbolAddress((void**)&xt, g_xT);
    cudaGetSymbolAddress((void**)&at, g_aT);
    cudaGetSymbolAddress((void**)&wq, g_wq);
    cudaGetSymbolAddress((void**)&wp, g_wp);

    // 0) mask dtype detection + bit packing
    detect_mask_dtype<<<1, 32>>>((const unsigned*)mask);
    pack_mask<<<(GG * PP * 8 + 255) / 256, 256>>>(mask);

    // 1) fp16 conversions: weights (round) + x^T (transposed round)
    conv_round<<<1024, 256>>>(w_qkv, wq, E3D * DD);
    conv_round<<<256, 256>>>(w_proj, wp, DD * DD);
    conv_xT<<<dim3(GP / 32, DD / 32, BB), dim3(32, 8)>>>(x);

    const int GEMM_SMEM = 3 * 20480;         // 60KB -> 2 CTAs/SM = 120KB
    cudaFuncSetAttribute((const void*)gemm_mma<__half>,
                         cudaFuncAttributeMaxDynamicSharedMemorySize, GEMM_SMEM);
    cudaFuncSetAttribute((const void*)gemm_mma<float>,
                         cudaFuncAttributeMaxDynamicSharedMemorySize, GEMM_SMEM);
    cudaFuncSetAttribute((const void*)attn_mma,
                         cudaFuncAttributeMaxDynamicSharedMemorySize, ATT_SMEM);

    // 2) QKV projection, 1-product fp16, fp16 output
    gemm_mma<__half><<<dim3(NT / 128, E3D / 128, BB), 256, GEMM_SMEM>>>(
        wq, xt, qkvbuf, nullptr, E3D);

    // 3) tensor-core flash attention per (b, h, g)
    attn_mma<<<dim3(GG, HH, BB), 256, ATT_SMEM>>>(qkvbuf);

    // 4) output projection + bias, 1-product fp16, fp32 output
    gemm_mma<float><<<dim3(NT / 128, DD / 128, BB), 256, GEMM_SMEM>>>(
        wp, at, out, b_proj, DD);
}